// round 7
// baseline (speedup 1.0000x reference)
#include <cuda_runtime.h>
#include <cuda_bf16.h>
#include <cstdint>

typedef __nv_bfloat16 bf16;

#define S_ 1024
#define T_ 1024
#define B_ 32
#define D_ 1024
#define A_ 1024

// ---------------------------------------------------------------------------
// Scratch (device globals; allocation is forbidden)
// ---------------------------------------------------------------------------
__device__ __align__(16) bf16 g_srcHi[(size_t)S_ * B_ * D_];   // (S,B,D)
__device__ __align__(16) bf16 g_srcLo[(size_t)S_ * B_ * D_];
__device__ __align__(16) bf16 g_tgtHi[(size_t)T_ * B_ * D_];   // (T,B,D)
__device__ __align__(16) bf16 g_tgtLo[(size_t)T_ * B_ * D_];
__device__ __align__(16) bf16 g_mtHi[(size_t)A_ * D_];         // Mt[e,d] = sum_a W2[a,e]W1[a,d]
__device__ __align__(16) bf16 g_mtLo[(size_t)A_ * D_];
__device__ __align__(16) bf16 g_uHi[(size_t)S_ * B_ * A_];     // (S,B,A) u = src @ Mt^T
__device__ __align__(16) bf16 g_uLo[(size_t)S_ * B_ * A_];
__device__ __align__(16) float g_sc[(size_t)B_ * T_ * S_];     // (B,T,S) scores
__device__ __align__(16) bf16 g_wHi[(size_t)B_ * T_ * S_];     // softmax weights split
__device__ __align__(16) bf16 g_wLo[(size_t)B_ * T_ * S_];

// ---------------------------------------------------------------------------
// Portable tensor-core primitives (sm_80-level PTX: safe for compute_103 pass)
// ---------------------------------------------------------------------------
__device__ __forceinline__ uint32_t smem_u32(const void* p) {
    uint32_t a;
    asm("{ .reg .u64 t; cvta.to.shared.u64 t, %1; cvt.u32.u64 %0, t; }" : "=r"(a) : "l"(p));
    return a;
}

__device__ __forceinline__ void cpa16(uint32_t s, const void* g) {
    asm volatile("cp.async.cg.shared.global [%0], [%1], 16;" :: "r"(s), "l"(g));
}
#define CP_COMMIT() asm volatile("cp.async.commit_group;" ::: "memory")
#define CP_WAIT1()  asm volatile("cp.async.wait_group 1;" ::: "memory")

__device__ __forceinline__ void ldsm4(uint32_t* r, uint32_t a) {
    asm volatile("ldmatrix.sync.aligned.m8n8.x4.shared.b16 {%0,%1,%2,%3}, [%4];"
                 : "=r"(r[0]), "=r"(r[1]), "=r"(r[2]), "=r"(r[3]) : "r"(a));
}
__device__ __forceinline__ void ldsm4t(uint32_t* r, uint32_t a) {
    asm volatile("ldmatrix.sync.aligned.m8n8.x4.trans.shared.b16 {%0,%1,%2,%3}, [%4];"
                 : "=r"(r[0]), "=r"(r[1]), "=r"(r[2]), "=r"(r[3]) : "r"(a));
}
__device__ __forceinline__ void mma_bf16(float* c, const uint32_t* a, const uint32_t* b) {
    asm volatile("mma.sync.aligned.m16n8k16.row.col.f32.bf16.bf16.f32 "
                 "{%0,%1,%2,%3}, {%4,%5,%6,%7}, {%8,%9}, {%0,%1,%2,%3};"
                 : "+f"(c[0]), "+f"(c[1]), "+f"(c[2]), "+f"(c[3])
                 : "r"(a[0]), "r"(a[1]), "r"(a[2]), "r"(a[3]), "r"(b[0]), "r"(b[1]));
}

// ---------------------------------------------------------------------------
// Tiled bf16x3-split GEMM:  C[m,n](z) = sum_k A[m,k]*B[n,k]  (NT)
//   or, if BTRANS:          C[m,n](z) = sum_k A[m,k]*B[k,n]  (B via ldmatrix.trans)
// CTA tile 256x128x32, 16 warps (4x4 grid of 64x32 warp tiles), 3-stage ring.
// MMA issue order keeps same-accumulator touches 8 MMAs apart (RAW distance).
// acc += Ahi*Bhi + Ahi*Blo + Alo*Bhi.
// ---------------------------------------------------------------------------
#define A_HALF   20480
#define BNT_HALF 10240
#define BTR_HALF 8704
#define STAGE_B  61440          // Ahi+Alo (40960) + Bhi+Blo (<=20480)
#define SM_TOTAL (3 * STAGE_B)  // 184320 B

__device__ __forceinline__ void load_A(uint32_t sbase, const bf16* g, long ld, int tid) {
    #pragma unroll
    for (int i = 0; i < 2; i++) {
        const int c = tid + i * 512;              // 1024 chunks of 16B
        const int row = c >> 2, off = (c & 3) * 8;
        cpa16(sbase + row * 80 + off * 2, g + (long)row * ld + off);
    }
}
__device__ __forceinline__ void load_B_nt(uint32_t sbase, const bf16* g, long ld, int tid) {
    const int row = tid >> 2, off = (tid & 3) * 8;  // 512 chunks of 16B
    cpa16(sbase + row * 80 + off * 2, g + (long)row * ld + off);
}
__device__ __forceinline__ void load_B_tr(uint32_t sbase, const bf16* g, long ld, int tid) {
    const int row = tid >> 4, off = (tid & 15) * 8; // 32 rows x 16 chunks
    cpa16(sbase + row * 272 + off * 2, g + (long)row * ld + off);
}

template <bool BTRANS, bool SPLITOUT>
__global__ __launch_bounds__(512, 1) void mma_gemm(
    const bf16* __restrict__ Ah, const bf16* __restrict__ Al,
    const bf16* __restrict__ Bh, const bf16* __restrict__ Bl,
    float* __restrict__ C, bf16* __restrict__ Oh, bf16* __restrict__ Ol,
    long lda, long ldb, long ldc, long aB, long bB, long cB)
{
    extern __shared__ char smem[];
    const uint32_t sb = smem_u32(smem);
    const int tid = threadIdx.x;
    const int lane = tid & 31, wid = tid >> 5;
    const int wy = wid >> 2, wx = wid & 3;        // 4 x 4 warps, 64x32 tiles
    const long m0 = (long)blockIdx.y * 256;
    const long n0 = (long)blockIdx.x * 128;
    const long z  = blockIdx.z;

    const bf16* pAh = Ah + z * aB + m0 * lda;
    const bf16* pAl = Al + z * aB + m0 * lda;
    const bf16* pBh = BTRANS ? (Bh + z * bB + n0) : (Bh + z * bB + n0 * ldb);
    const bf16* pBl = BTRANS ? (Bl + z * bB + n0) : (Bl + z * bB + n0 * ldb);

    float acc[4][4][4] = {};

    auto LOAD = [&](int chunk) {
        const uint32_t st = sb + (chunk % 3) * STAGE_B;
        const long k0 = (long)chunk * 32;
        load_A(st,          pAh + k0, lda, tid);
        load_A(st + A_HALF, pAl + k0, lda, tid);
        if (BTRANS) {
            load_B_tr(st + 2 * A_HALF,            pBh + k0 * ldb, ldb, tid);
            load_B_tr(st + 2 * A_HALF + BTR_HALF, pBl + k0 * ldb, ldb, tid);
        } else {
            load_B_nt(st + 2 * A_HALF,            pBh + k0, ldb, tid);
            load_B_nt(st + 2 * A_HALF + BNT_HALF, pBl + k0, ldb, tid);
        }
    };

    // k16-invariant address parts
    const uint32_t aRow0   = (uint32_t)(wy * 64 + (lane & 15)) * 80 + ((lane >> 4) << 4);
    const uint32_t bRowNT0 = (uint32_t)(wx * 32 + (lane & 7) + ((lane >> 4) << 3)) * 80
                           + (((lane >> 3) & 1) << 4);
    const uint32_t bColTR  = (uint32_t)(wx * 32 + ((lane >> 4) << 3)) * 2;
    const uint32_t bRowTR0 = (uint32_t)((lane & 7) + ((lane >> 3) & 1) * 8) * 272;

    LOAD(0); CP_COMMIT();
    LOAD(1); CP_COMMIT();

    const int NC = 32;   // K = 1024 / 32
    for (int c = 0; c < NC; c++) {
        CP_WAIT1();                       // chunk c resident (c+1 may fly)
        __syncthreads();                  // all warps done with stage (c-1)%3
        if (c + 2 < NC) LOAD(c + 2);      // refill stage (c-1)%3
        CP_COMMIT();
        const uint32_t st = sb + (c % 3) * STAGE_B;

        #pragma unroll
        for (int k16 = 0; k16 < 2; k16++) {
            const uint32_t kb = (uint32_t)k16 * 32;
            uint32_t bh[8], bl[8];
            if (!BTRANS) {
                #pragma unroll
                for (int p = 0; p < 2; p++) {
                    const uint32_t bd = st + 2 * A_HALF + bRowNT0 + (uint32_t)p * 16 * 80 + kb;
                    ldsm4(&bh[p * 4], bd);
                    ldsm4(&bl[p * 4], bd + BNT_HALF);
                }
            } else {
                #pragma unroll
                for (int p = 0; p < 2; p++) {
                    const uint32_t bd = st + 2 * A_HALF + bRowTR0 + (uint32_t)k16 * 16 * 272
                                      + bColTR + (uint32_t)p * 32;
                    ldsm4t(&bh[p * 4], bd);
                    ldsm4t(&bl[p * 4], bd + BTR_HALF);
                }
            }
            // Process mt in pairs; splits outermost -> same-acc RAW distance = 8 MMAs
            #pragma unroll
            for (int mp = 0; mp < 2; mp++) {
                uint32_t ah[2][4], al[2][4];
                #pragma unroll
                for (int i = 0; i < 2; i++) {
                    const uint32_t ad = st + aRow0 + (uint32_t)(mp * 2 + i) * 16 * 80 + kb;
                    ldsm4(ah[i], ad);
                    ldsm4(al[i], ad + A_HALF);
                }
                #pragma unroll
                for (int i = 0; i < 2; i++)
                    #pragma unroll
                    for (int nt = 0; nt < 4; nt++)
                        mma_bf16(acc[mp * 2 + i][nt], ah[i], &bh[nt * 2]);
                #pragma unroll
                for (int i = 0; i < 2; i++)
                    #pragma unroll
                    for (int nt = 0; nt < 4; nt++)
                        mma_bf16(acc[mp * 2 + i][nt], ah[i], &bl[nt * 2]);
                #pragma unroll
                for (int i = 0; i < 2; i++)
                    #pragma unroll
                    for (int nt = 0; nt < 4; nt++)
                        mma_bf16(acc[mp * 2 + i][nt], al[i], &bh[nt * 2]);
            }
        }
    }

    // Epilogue (registers -> gmem)
    #pragma unroll
    for (int mt = 0; mt < 4; mt++) {
        #pragma unroll
        for (int half = 0; half < 2; half++) {
            const long row = m0 + wy * 64 + mt * 16 + (lane >> 2) + half * 8;
            #pragma unroll
            for (int nt = 0; nt < 4; nt++) {
                const long col = n0 + wx * 32 + nt * 8 + (lane & 3) * 2;
                const float v0 = acc[mt][nt][half * 2 + 0];
                const float v1 = acc[mt][nt][half * 2 + 1];
                if (SPLITOUT) {
                    bf16 h0 = __float2bfloat16_rn(v0), h1 = __float2bfloat16_rn(v1);
                    bf16 l0 = __float2bfloat16_rn(v0 - __bfloat162float(h0));
                    bf16 l1 = __float2bfloat16_rn(v1 - __bfloat162float(h1));
                    __nv_bfloat162 hv(h0, h1), lv(l0, l1);
                    *(uint32_t*)(Oh + z * cB + row * ldc + col) = *(uint32_t*)&hv;
                    *(uint32_t*)(Ol + z * cB + row * ldc + col) = *(uint32_t*)&lv;
                } else {
                    *(float2*)(C + z * cB + row * ldc + col) = make_float2(v0, v1);
                }
            }
        }
    }
}

// ---------------------------------------------------------------------------
// Elementwise fp32 -> bf16 hi/lo split
// ---------------------------------------------------------------------------
__global__ __launch_bounds__(256) void split_kernel(
    const float* __restrict__ x, bf16* __restrict__ hi, bf16* __restrict__ lo)
{
    const size_t i4 = (size_t)blockIdx.x * 256 + threadIdx.x;
    float4 v = ((const float4*)x)[i4];
    float f[4] = {v.x, v.y, v.z, v.w};
    uint32_t hw[2], lw[2];
    #pragma unroll
    for (int p = 0; p < 2; p++) {
        bf16 h0 = __float2bfloat16_rn(f[2 * p]), h1 = __float2bfloat16_rn(f[2 * p + 1]);
        bf16 l0 = __float2bfloat16_rn(f[2 * p] - __bfloat162float(h0));
        bf16 l1 = __float2bfloat16_rn(f[2 * p + 1] - __bfloat162float(h1));
        __nv_bfloat162 hv(h0, h1), lv(l0, l1);
        hw[p] = *(uint32_t*)&hv;
        lw[p] = *(uint32_t*)&lv;
    }
    ((uint2*)hi)[i4] = make_uint2(hw[0], hw[1]);
    ((uint2*)lo)[i4] = make_uint2(lw[0], lw[1]);
}

// ---------------------------------------------------------------------------
// TN SIMT fp32 GEMM: Mt[e,d] = sum_a W2[a,e]*W1[a,d], split-stored (2 GFLOP)
// ---------------------------------------------------------------------------
__global__ __launch_bounds__(256) void tn_split_kernel(
    const float* __restrict__ W2, const float* __restrict__ W1)
{
    __shared__ float As[16][128];
    __shared__ float Bs[16][128];

    const int tid = threadIdx.x;
    const int tx = tid & 15, ty = tid >> 4;
    const int m0 = blockIdx.y * 128, n0 = blockIdx.x * 128;
    const int r8 = tid >> 5, c4 = (tid & 31) * 4;

    float acc[8][8] = {};

    for (int k0 = 0; k0 < 1024; k0 += 16) {
        #pragma unroll
        for (int i = 0; i < 2; i++) {
            const int kr = k0 + r8 + i * 8;
            *(float4*)&As[r8 + i * 8][c4] = *(const float4*)(W2 + (size_t)kr * 1024 + m0 + c4);
            *(float4*)&Bs[r8 + i * 8][c4] = *(const float4*)(W1 + (size_t)kr * 1024 + n0 + c4);
        }
        __syncthreads();
        #pragma unroll
        for (int kk = 0; kk < 16; kk++) {
            float ra[8], rb[8];
            *(float4*)&ra[0] = *(const float4*)&As[kk][ty * 8];
            *(float4*)&ra[4] = *(const float4*)&As[kk][ty * 8 + 4];
            *(float4*)&rb[0] = *(const float4*)&Bs[kk][tx * 8];
            *(float4*)&rb[4] = *(const float4*)&Bs[kk][tx * 8 + 4];
            #pragma unroll
            for (int i = 0; i < 8; i++)
                #pragma unroll
                for (int j = 0; j < 8; j++)
                    acc[i][j] = fmaf(ra[i], rb[j], acc[i][j]);
        }
        __syncthreads();
    }

    #pragma unroll
    for (int i = 0; i < 8; i++) {
        const size_t base = (size_t)(m0 + ty * 8 + i) * 1024 + n0 + tx * 8;
        #pragma unroll
        for (int j = 0; j < 8; j++) {
            float f = acc[i][j];
            bf16 h = __float2bfloat16_rn(f);
            g_mtHi[base + j] = h;
            g_mtLo[base + j] = __float2bfloat16_rn(f - __bfloat162float(h));
        }
    }
}

// ---------------------------------------------------------------------------
// Softmax over contiguous rows of 1024; writes bf16 hi/lo split weights.
// ---------------------------------------------------------------------------
__global__ __launch_bounds__(256) void softmax_split_kernel(const float* __restrict__ sc)
{
    const size_t row = blockIdx.x;
    const float4* p = (const float4*)(sc + row * 1024);
    const int tid = threadIdx.x;
    __shared__ float sh[8];

    float4 v = p[tid];

    float m = fmaxf(fmaxf(v.x, v.y), fmaxf(v.z, v.w));
    #pragma unroll
    for (int o = 16; o; o >>= 1) m = fmaxf(m, __shfl_xor_sync(0xffffffffu, m, o));
    if ((tid & 31) == 0) sh[tid >> 5] = m;
    __syncthreads();
    m = sh[0];
    #pragma unroll
    for (int i = 1; i < 8; i++) m = fmaxf(m, sh[i]);
    __syncthreads();

    v.x = __expf(v.x - m); v.y = __expf(v.y - m);
    v.z = __expf(v.z - m); v.w = __expf(v.w - m);
    float s = v.x + v.y + v.z + v.w;
    #pragma unroll
    for (int o = 16; o; o >>= 1) s += __shfl_xor_sync(0xffffffffu, s, o);
    if ((tid & 31) == 0) sh[tid >> 5] = s;
    __syncthreads();
    s = sh[0] + sh[1] + sh[2] + sh[3] + sh[4] + sh[5] + sh[6] + sh[7];
    const float inv = 1.0f / s;

    float f[4] = {v.x * inv, v.y * inv, v.z * inv, v.w * inv};
    uint32_t hw[2], lw[2];
    #pragma unroll
    for (int q = 0; q < 2; q++) {
        bf16 h0 = __float2bfloat16_rn(f[2 * q]), h1 = __float2bfloat16_rn(f[2 * q + 1]);
        bf16 l0 = __float2bfloat16_rn(f[2 * q] - __bfloat162float(h0));
        bf16 l1 = __float2bfloat16_rn(f[2 * q + 1] - __bfloat162float(h1));
        __nv_bfloat162 hv(h0, h1), lv(l0, l1);
        hw[q] = *(uint32_t*)&hv;
        lw[q] = *(uint32_t*)&lv;
    }
    ((uint2*)(g_wHi + row * 1024))[tid] = make_uint2(hw[0], hw[1]);
    ((uint2*)(g_wLo + row * 1024))[tid] = make_uint2(lw[0], lw[1]);
}

// ---------------------------------------------------------------------------
// Host
// ---------------------------------------------------------------------------
extern "C" void kernel_launch(void* const* d_in, const int* in_sizes, int n_in,
                              void* d_out, int out_size)
{
    const float* src = (const float*)d_in[0];  // (S,B,D)
    const float* tgt = (const float*)d_in[1];  // (T,B,D)
    const float* W1  = (const float*)d_in[2];  // (A,D)
    const float* W2  = (const float*)d_in[3];  // (A,D)
    float* out = (float*)d_out;                // (T,B,D)

    void *srcHi, *srcLo, *tgtHi, *tgtLo, *mtHi, *mtLo, *uHi, *uLo, *sc, *wHi, *wLo;
    cudaGetSymbolAddress(&srcHi, g_srcHi); cudaGetSymbolAddress(&srcLo, g_srcLo);
    cudaGetSymbolAddress(&tgtHi, g_tgtHi); cudaGetSymbolAddress(&tgtLo, g_tgtLo);
    cudaGetSymbolAddress(&mtHi, g_mtHi);   cudaGetSymbolAddress(&mtLo, g_mtLo);
    cudaGetSymbolAddress(&uHi, g_uHi);     cudaGetSymbolAddress(&uLo, g_uLo);
    cudaGetSymbolAddress(&sc, g_sc);
    cudaGetSymbolAddress(&wHi, g_wHi);     cudaGetSymbolAddress(&wLo, g_wLo);

    cudaFuncSetAttribute(mma_gemm<false, true>,  cudaFuncAttributeMaxDynamicSharedMemorySize, SM_TOTAL);
    cudaFuncSetAttribute(mma_gemm<false, false>, cudaFuncAttributeMaxDynamicSharedMemorySize, SM_TOTAL);
    cudaFuncSetAttribute(mma_gemm<true,  false>, cudaFuncAttributeMaxDynamicSharedMemorySize, SM_TOTAL);

    // 1-2. split source & target into bf16 hi/lo
    split_kernel<<<(S_ * B_ * D_ / 4) / 256, 256>>>(src, (bf16*)srcHi, (bf16*)srcLo);
    split_kernel<<<(T_ * B_ * D_ / 4) / 256, 256>>>(tgt, (bf16*)tgtHi, (bf16*)tgtLo);
    // 3. Mt = W2^T W1 (fp32 SIMT), split-stored
    tn_split_kernel<<<dim3(8, 8), 256>>>(W2, W1);

    // 4. u[(s,b), e] = sum_d src[(s,b), d] * Mt[e, d]   (NT, M=32768, split output)
    mma_gemm<false, true><<<dim3(8, 128, 1), 512, SM_TOTAL>>>(
        (const bf16*)srcHi, (const bf16*)srcLo, (const bf16*)mtHi, (const bf16*)mtLo,
        nullptr, (bf16*)uHi, (bf16*)uLo,
        1024, 1024, 1024, 0, 0, 0);

    // 5. scores[b,t,s] = sum_e tgt[t,b,e] * u[s,b,e]   (NT, batched over b)
    mma_gemm<false, false><<<dim3(8, 4, 32), 512, SM_TOTAL>>>(
        (const bf16*)tgtHi, (const bf16*)tgtLo, (const bf16*)uHi, (const bf16*)uLo,
        (float*)sc, nullptr, nullptr,
        32768, 32768, 1024, 1024, 1024, (long)1024 * 1024);

    // 6. softmax over s (+ split weights)
    softmax_split_kernel<<<B_ * T_, 256>>>((const float*)sc);

    // 7. out[t,b,d] = sum_s w[b,t,s] * src[s,b,d]   (A NT, B via ldmatrix.trans)
    mma_gemm<true, false><<<dim3(8, 4, 32), 512, SM_TOTAL>>>(
        (const bf16*)wHi, (const bf16*)wLo, (const bf16*)srcHi, (const bf16*)srcLo,
        out, nullptr, nullptr,
        1024, 32768, 32768, (long)1024 * 1024, 1024, 1024);
}

// round 8
// speedup vs baseline: 1.1310x; 1.1310x over previous
#include <cuda_runtime.h>
#include <cuda_bf16.h>
#include <cstdint>

typedef __nv_bfloat16 bf16;

#define S_ 1024
#define T_ 1024
#define B_ 32
#define D_ 1024
#define A_ 1024

// ---------------------------------------------------------------------------
// Scratch (device globals; allocation is forbidden)
// ---------------------------------------------------------------------------
__device__ __align__(16) bf16 g_srcHi[(size_t)S_ * B_ * D_];   // (S,B,D)
__device__ __align__(16) bf16 g_srcLo[(size_t)S_ * B_ * D_];
__device__ __align__(16) bf16 g_tgtHi[(size_t)T_ * B_ * D_];   // (T,B,D)
__device__ __align__(16) bf16 g_tgtLo[(size_t)T_ * B_ * D_];
__device__ __align__(16) bf16 g_mtHi[(size_t)A_ * D_];         // Mt[e,d] = sum_a W2[a,e]W1[a,d]
__device__ __align__(16) bf16 g_mtLo[(size_t)A_ * D_];
__device__ __align__(16) bf16 g_uHi[(size_t)S_ * B_ * A_];     // (S,B,A) u = src @ Mt^T
__device__ __align__(16) bf16 g_uLo[(size_t)S_ * B_ * A_];
__device__ __align__(16) float g_sc[(size_t)B_ * T_ * S_];     // (B,T,S) scores
__device__ __align__(16) bf16 g_wHi[(size_t)B_ * T_ * S_];     // softmax weights split
__device__ __align__(16) bf16 g_wLo[(size_t)B_ * T_ * S_];

// ---------------------------------------------------------------------------
// Portable tensor-core primitives (sm_80-level PTX: safe for compute_103 pass)
// ---------------------------------------------------------------------------
__device__ __forceinline__ uint32_t smem_u32(const void* p) {
    uint32_t a;
    asm("{ .reg .u64 t; cvta.to.shared.u64 t, %1; cvt.u32.u64 %0, t; }" : "=r"(a) : "l"(p));
    return a;
}

__device__ __forceinline__ void cpa16(uint32_t s, const void* g) {
    asm volatile("cp.async.cg.shared.global [%0], [%1], 16;" :: "r"(s), "l"(g));
}
#define CP_COMMIT() asm volatile("cp.async.commit_group;" ::: "memory")
#define CP_WAIT1()  asm volatile("cp.async.wait_group 1;" ::: "memory")

__device__ __forceinline__ void ldsm4(uint32_t* r, uint32_t a) {
    asm volatile("ldmatrix.sync.aligned.m8n8.x4.shared.b16 {%0,%1,%2,%3}, [%4];"
                 : "=r"(r[0]), "=r"(r[1]), "=r"(r[2]), "=r"(r[3]) : "r"(a));
}
__device__ __forceinline__ void ldsm4t(uint32_t* r, uint32_t a) {
    asm volatile("ldmatrix.sync.aligned.m8n8.x4.trans.shared.b16 {%0,%1,%2,%3}, [%4];"
                 : "=r"(r[0]), "=r"(r[1]), "=r"(r[2]), "=r"(r[3]) : "r"(a));
}
__device__ __forceinline__ void mma_bf16(float* c, const uint32_t* a, const uint32_t* b) {
    asm volatile("mma.sync.aligned.m16n8k16.row.col.f32.bf16.bf16.f32 "
                 "{%0,%1,%2,%3}, {%4,%5,%6,%7}, {%8,%9}, {%0,%1,%2,%3};"
                 : "+f"(c[0]), "+f"(c[1]), "+f"(c[2]), "+f"(c[3])
                 : "r"(a[0]), "r"(a[1]), "r"(a[2]), "r"(a[3]), "r"(b[0]), "r"(b[1]));
}

// ---------------------------------------------------------------------------
// Tiled bf16x3-split GEMM:  C[m,n](z) = sum_k A[m,k]*B[n,k]  (NT)
//   or, if BTRANS:          C[m,n](z) = sum_k A[m,k]*B[k,n]  (B via ldmatrix.trans)
// CTA tile 128x128x32, 8 warps (2x4 grid of 64x32 warp tiles), 3-stage ring,
// 2 CTAs/SM (barrier stagger). XOR-swizzled smem (no padding):
//   NT tiles: 128 rows x 64B, chunk' = chunk ^ ((row>>1)&3)
//   TR tile :  32 rows x 256B, chunk' = chunk ^ (row&7)
// acc += Ahi*Bhi + Ahi*Blo + Alo*Bhi.
// ---------------------------------------------------------------------------
#define HALF_B   8192           // one NT half (128x64B) or TR half (32x256B)
#define STAGE_B  32768          // Ahi, Alo, Bhi, Blo
#define SM_TOTAL (3 * STAGE_B)  // 98304 B per CTA

// NT tile store: 512 chunks of 16B (128 rows x 4 chunks), 256 threads -> 2 iters
__device__ __forceinline__ void load_nt(uint32_t sbase, const bf16* g, long ld, int tid) {
    #pragma unroll
    for (int i = 0; i < 2; i++) {
        const int c = tid + i * 256;
        const int row = c >> 2, ch = c & 3;
        const int sw = ch ^ ((row >> 1) & 3);
        cpa16(sbase + row * 64 + sw * 16, g + (long)row * ld + ch * 8);
    }
}
// TR tile store: 512 chunks (32 rows x 16 chunks)
__device__ __forceinline__ void load_tr(uint32_t sbase, const bf16* g, long ld, int tid) {
    #pragma unroll
    for (int i = 0; i < 2; i++) {
        const int c = tid + i * 256;
        const int row = c >> 4, ch = c & 15;
        const int sw = ch ^ (row & 7);
        cpa16(sbase + row * 256 + sw * 16, g + (long)row * ld + ch * 8);
    }
}

template <bool BTRANS, bool SPLITOUT>
__global__ __launch_bounds__(256, 2) void mma_gemm(
    const bf16* __restrict__ Ah, const bf16* __restrict__ Al,
    const bf16* __restrict__ Bh, const bf16* __restrict__ Bl,
    float* __restrict__ C, bf16* __restrict__ Oh, bf16* __restrict__ Ol,
    long lda, long ldb, long ldc, long aB, long bB, long cB)
{
    extern __shared__ char smem[];
    const uint32_t sb = smem_u32(smem);
    const int tid = threadIdx.x;
    const int lane = tid & 31, wid = tid >> 5;
    const int wy = wid >> 2, wx = wid & 3;        // 2 x 4 warps, 64x32 tiles
    const long m0 = (long)blockIdx.y * 128;
    const long n0 = (long)blockIdx.x * 128;
    const long z  = blockIdx.z;

    const bf16* pAh = Ah + z * aB + m0 * lda;
    const bf16* pAl = Al + z * aB + m0 * lda;
    const bf16* pBh = BTRANS ? (Bh + z * bB + n0) : (Bh + z * bB + n0 * ldb);
    const bf16* pBl = BTRANS ? (Bl + z * bB + n0) : (Bl + z * bB + n0 * ldb);

    float acc[4][4][4] = {};

    auto LOAD = [&](int chunk) {
        const uint32_t st = sb + (chunk % 3) * STAGE_B;
        const long k0 = (long)chunk * 32;
        load_nt(st,          pAh + k0, lda, tid);
        load_nt(st + HALF_B, pAl + k0, lda, tid);
        if (BTRANS) {
            load_tr(st + 2 * HALF_B, pBh + k0 * ldb, ldb, tid);
            load_tr(st + 3 * HALF_B, pBl + k0 * ldb, ldb, tid);
        } else {
            load_nt(st + 2 * HALF_B, pBh + k0, ldb, tid);
            load_nt(st + 3 * HALF_B, pBl + k0, ldb, tid);
        }
    };

    // Thread-constant ldsm address components (swizzle folded in)
    const int hi4 = lane >> 4;                     // 0/1 : 16B half selector
    // A: row = wy*64 + mt*16 + (lane&15); swizzle key sA const across mt/k16
    const uint32_t aRowB = (uint32_t)(wy * 64 + (lane & 15)) * 64;
    const int sA = ((lane & 15) >> 1) & 3;
    // B NT: row = wx*32 + p*16 + (lane&7) + ((lane>>4)<<3); chunk sel (lane>>3)&1
    const uint32_t bRowB = (uint32_t)(wx * 32 + (lane & 7) + (hi4 << 3)) * 64;
    const int sB = (((lane & 7) + (hi4 << 3)) >> 1) & 3;
    const int bSel = (lane >> 3) & 1;
    // B TR: row = k16*16 + (lane&7) + ((lane>>3)&1)*8; chunk = wx*4 + p*2 + hi4
    const uint32_t trRowB = (uint32_t)((lane & 7) + bSel * 8) * 256;
    const uint32_t trC0 = (uint32_t)((wx * 4 + 0 + hi4) ^ (lane & 7)) * 16;
    const uint32_t trC1 = (uint32_t)((wx * 4 + 2 + hi4) ^ (lane & 7)) * 16;

    LOAD(0); CP_COMMIT();
    LOAD(1); CP_COMMIT();

    const int NC = 32;   // K = 1024 / 32
    for (int c = 0; c < NC; c++) {
        CP_WAIT1();                       // chunk c resident (c+1 may fly)
        __syncthreads();                  // all warps done with stage (c-1)%3
        if (c + 2 < NC) LOAD(c + 2);      // refill stage (c-1)%3
        CP_COMMIT();
        const uint32_t st = sb + (c % 3) * STAGE_B;

        #pragma unroll
        for (int k16 = 0; k16 < 2; k16++) {
            uint32_t bh[8], bl[8];
            if (!BTRANS) {
                const uint32_t cOff = (uint32_t)((k16 * 2 + bSel) ^ sB) * 16;
                #pragma unroll
                for (int p = 0; p < 2; p++) {
                    const uint32_t bd = st + 2 * HALF_B + bRowB + (uint32_t)p * 16 * 64 + cOff;
                    ldsm4(&bh[p * 4], bd);
                    ldsm4(&bl[p * 4], bd + HALF_B);
                }
            } else {
                const uint32_t rOff = trRowB + (uint32_t)k16 * 16 * 256;
                ldsm4t(&bh[0], st + 2 * HALF_B + rOff + trC0);
                ldsm4t(&bh[4], st + 2 * HALF_B + rOff + trC1);
                ldsm4t(&bl[0], st + 3 * HALF_B + rOff + trC0);
                ldsm4t(&bl[4], st + 3 * HALF_B + rOff + trC1);
            }
            const uint32_t aOff = (uint32_t)((k16 * 2 + hi4) ^ sA) * 16;
            #pragma unroll
            for (int mt = 0; mt < 4; mt++) {
                uint32_t ah[4], al[4];
                const uint32_t ad = st + aRowB + (uint32_t)mt * 16 * 64 + aOff;
                ldsm4(ah, ad);
                ldsm4(al, ad + HALF_B);
                #pragma unroll
                for (int nt = 0; nt < 4; nt++) {
                    mma_bf16(acc[mt][nt], ah, &bh[nt * 2]);
                    mma_bf16(acc[mt][nt], ah, &bl[nt * 2]);
                    mma_bf16(acc[mt][nt], al, &bh[nt * 2]);
                }
            }
        }
    }

    // Epilogue (registers -> gmem)
    #pragma unroll
    for (int mt = 0; mt < 4; mt++) {
        #pragma unroll
        for (int half = 0; half < 2; half++) {
            const long row = m0 + wy * 64 + mt * 16 + (lane >> 2) + half * 8;
            #pragma unroll
            for (int nt = 0; nt < 4; nt++) {
                const long col = n0 + wx * 32 + nt * 8 + (lane & 3) * 2;
                const float v0 = acc[mt][nt][half * 2 + 0];
                const float v1 = acc[mt][nt][half * 2 + 1];
                if (SPLITOUT) {
                    bf16 h0 = __float2bfloat16_rn(v0), h1 = __float2bfloat16_rn(v1);
                    bf16 l0 = __float2bfloat16_rn(v0 - __bfloat162float(h0));
                    bf16 l1 = __float2bfloat16_rn(v1 - __bfloat162float(h1));
                    __nv_bfloat162 hv(h0, h1), lv(l0, l1);
                    *(uint32_t*)(Oh + z * cB + row * ldc + col) = *(uint32_t*)&hv;
                    *(uint32_t*)(Ol + z * cB + row * ldc + col) = *(uint32_t*)&lv;
                } else {
                    *(float2*)(C + z * cB + row * ldc + col) = make_float2(v0, v1);
                }
            }
        }
    }
}

// ---------------------------------------------------------------------------
// Elementwise fp32 -> bf16 hi/lo split
// ---------------------------------------------------------------------------
__global__ __launch_bounds__(256) void split_kernel(
    const float* __restrict__ x, bf16* __restrict__ hi, bf16* __restrict__ lo)
{
    const size_t i4 = (size_t)blockIdx.x * 256 + threadIdx.x;
    float4 v = ((const float4*)x)[i4];
    float f[4] = {v.x, v.y, v.z, v.w};
    uint32_t hw[2], lw[2];
    #pragma unroll
    for (int p = 0; p < 2; p++) {
        bf16 h0 = __float2bfloat16_rn(f[2 * p]), h1 = __float2bfloat16_rn(f[2 * p + 1]);
        bf16 l0 = __float2bfloat16_rn(f[2 * p] - __bfloat162float(h0));
        bf16 l1 = __float2bfloat16_rn(f[2 * p + 1] - __bfloat162float(h1));
        __nv_bfloat162 hv(h0, h1), lv(l0, l1);
        hw[p] = *(uint32_t*)&hv;
        lw[p] = *(uint32_t*)&lv;
    }
    ((uint2*)hi)[i4] = make_uint2(hw[0], hw[1]);
    ((uint2*)lo)[i4] = make_uint2(lw[0], lw[1]);
}

// ---------------------------------------------------------------------------
// TN SIMT fp32 GEMM: Mt[e,d] = sum_a W2[a,e]*W1[a,d], split-stored (2 GFLOP)
// ---------------------------------------------------------------------------
__global__ __launch_bounds__(256) void tn_split_kernel(
    const float* __restrict__ W2, const float* __restrict__ W1)
{
    __shared__ float As[16][128];
    __shared__ float Bs[16][128];

    const int tid = threadIdx.x;
    const int tx = tid & 15, ty = tid >> 4;
    const int m0 = blockIdx.y * 128, n0 = blockIdx.x * 128;
    const int r8 = tid >> 5, c4 = (tid & 31) * 4;

    float acc[8][8] = {};

    for (int k0 = 0; k0 < 1024; k0 += 16) {
        #pragma unroll
        for (int i = 0; i < 2; i++) {
            const int kr = k0 + r8 + i * 8;
            *(float4*)&As[r8 + i * 8][c4] = *(const float4*)(W2 + (size_t)kr * 1024 + m0 + c4);
            *(float4*)&Bs[r8 + i * 8][c4] = *(const float4*)(W1 + (size_t)kr * 1024 + n0 + c4);
        }
        __syncthreads();
        #pragma unroll
        for (int kk = 0; kk < 16; kk++) {
            float ra[8], rb[8];
            *(float4*)&ra[0] = *(const float4*)&As[kk][ty * 8];
            *(float4*)&ra[4] = *(const float4*)&As[kk][ty * 8 + 4];
            *(float4*)&rb[0] = *(const float4*)&Bs[kk][tx * 8];
            *(float4*)&rb[4] = *(const float4*)&Bs[kk][tx * 8 + 4];
            #pragma unroll
            for (int i = 0; i < 8; i++)
                #pragma unroll
                for (int j = 0; j < 8; j++)
                    acc[i][j] = fmaf(ra[i], rb[j], acc[i][j]);
        }
        __syncthreads();
    }

    #pragma unroll
    for (int i = 0; i < 8; i++) {
        const size_t base = (size_t)(m0 + ty * 8 + i) * 1024 + n0 + tx * 8;
        #pragma unroll
        for (int j = 0; j < 8; j++) {
            float f = acc[i][j];
            bf16 h = __float2bfloat16_rn(f);
            g_mtHi[base + j] = h;
            g_mtLo[base + j] = __float2bfloat16_rn(f - __bfloat162float(h));
        }
    }
}

// ---------------------------------------------------------------------------
// Softmax over contiguous rows of 1024; writes bf16 hi/lo split weights.
// ---------------------------------------------------------------------------
__global__ __launch_bounds__(256) void softmax_split_kernel(const float* __restrict__ sc)
{
    const size_t row = blockIdx.x;
    const float4* p = (const float4*)(sc + row * 1024);
    const int tid = threadIdx.x;
    __shared__ float sh[8];

    float4 v = p[tid];

    float m = fmaxf(fmaxf(v.x, v.y), fmaxf(v.z, v.w));
    #pragma unroll
    for (int o = 16; o; o >>= 1) m = fmaxf(m, __shfl_xor_sync(0xffffffffu, m, o));
    if ((tid & 31) == 0) sh[tid >> 5] = m;
    __syncthreads();
    m = sh[0];
    #pragma unroll
    for (int i = 1; i < 8; i++) m = fmaxf(m, sh[i]);
    __syncthreads();

    v.x = __expf(v.x - m); v.y = __expf(v.y - m);
    v.z = __expf(v.z - m); v.w = __expf(v.w - m);
    float s = v.x + v.y + v.z + v.w;
    #pragma unroll
    for (int o = 16; o; o >>= 1) s += __shfl_xor_sync(0xffffffffu, s, o);
    if ((tid & 31) == 0) sh[tid >> 5] = s;
    __syncthreads();
    s = sh[0] + sh[1] + sh[2] + sh[3] + sh[4] + sh[5] + sh[6] + sh[7];
    const float inv = 1.0f / s;

    float f[4] = {v.x * inv, v.y * inv, v.z * inv, v.w * inv};
    uint32_t hw[2], lw[2];
    #pragma unroll
    for (int q = 0; q < 2; q++) {
        bf16 h0 = __float2bfloat16_rn(f[2 * q]), h1 = __float2bfloat16_rn(f[2 * q + 1]);
        bf16 l0 = __float2bfloat16_rn(f[2 * q] - __bfloat162float(h0));
        bf16 l1 = __float2bfloat16_rn(f[2 * q + 1] - __bfloat162float(h1));
        __nv_bfloat162 hv(h0, h1), lv(l0, l1);
        hw[q] = *(uint32_t*)&hv;
        lw[q] = *(uint32_t*)&lv;
    }
    ((uint2*)(g_wHi + row * 1024))[tid] = make_uint2(hw[0], hw[1]);
    ((uint2*)(g_wLo + row * 1024))[tid] = make_uint2(lw[0], lw[1]);
}

// ---------------------------------------------------------------------------
// Host
// ---------------------------------------------------------------------------
extern "C" void kernel_launch(void* const* d_in, const int* in_sizes, int n_in,
                              void* d_out, int out_size)
{
    const float* src = (const float*)d_in[0];  // (S,B,D)
    const float* tgt = (const float*)d_in[1];  // (T,B,D)
    const float* W1  = (const float*)d_in[2];  // (A,D)
    const float* W2  = (const float*)d_in[3];  // (A,D)
    float* out = (float*)d_out;                // (T,B,D)

    void *srcHi, *srcLo, *tgtHi, *tgtLo, *mtHi, *mtLo, *uHi, *uLo, *sc, *wHi, *wLo;
    cudaGetSymbolAddress(&srcHi, g_srcHi); cudaGetSymbolAddress(&srcLo, g_srcLo);
    cudaGetSymbolAddress(&tgtHi, g_tgtHi); cudaGetSymbolAddress(&tgtLo, g_tgtLo);
    cudaGetSymbolAddress(&mtHi, g_mtHi);   cudaGetSymbolAddress(&mtLo, g_mtLo);
    cudaGetSymbolAddress(&uHi, g_uHi);     cudaGetSymbolAddress(&uLo, g_uLo);
    cudaGetSymbolAddress(&sc, g_sc);
    cudaGetSymbolAddress(&wHi, g_wHi);     cudaGetSymbolAddress(&wLo, g_wLo);

    cudaFuncSetAttribute(mma_gemm<false, true>,  cudaFuncAttributeMaxDynamicSharedMemorySize, SM_TOTAL);
    cudaFuncSetAttribute(mma_gemm<false, false>, cudaFuncAttributeMaxDynamicSharedMemorySize, SM_TOTAL);
    cudaFuncSetAttribute(mma_gemm<true,  false>, cudaFuncAttributeMaxDynamicSharedMemorySize, SM_TOTAL);

    // 1-2. split source & target into bf16 hi/lo
    split_kernel<<<(S_ * B_ * D_ / 4) / 256, 256>>>(src, (bf16*)srcHi, (bf16*)srcLo);
    split_kernel<<<(T_ * B_ * D_ / 4) / 256, 256>>>(tgt, (bf16*)tgtHi, (bf16*)tgtLo);
    // 3. Mt = W2^T W1 (fp32 SIMT), split-stored
    tn_split_kernel<<<dim3(8, 8), 256>>>(W2, W1);

    // 4. u[(s,b), e] = sum_d src[(s,b), d] * Mt[e, d]   (NT, M=32768, split output)
    mma_gemm<false, true><<<dim3(8, 256, 1), 256, SM_TOTAL>>>(
        (const bf16*)srcHi, (const bf16*)srcLo, (const bf16*)mtHi, (const bf16*)mtLo,
        nullptr, (bf16*)uHi, (bf16*)uLo,
        1024, 1024, 1024, 0, 0, 0);

    // 5. scores[b,t,s] = sum_e tgt[t,b,e] * u[s,b,e]   (NT, batched over b)
    mma_gemm<false, false><<<dim3(8, 8, 32), 256, SM_TOTAL>>>(
        (const bf16*)tgtHi, (const bf16*)tgtLo, (const bf16*)uHi, (const bf16*)uLo,
        (float*)sc, nullptr, nullptr,
        32768, 32768, 1024, 1024, 1024, (long)1024 * 1024);

    // 6. softmax over s (+ split weights)
    softmax_split_kernel<<<B_ * T_, 256>>>((const float*)sc);

    // 7. out[t,b,d] = sum_s w[b,t,s] * src[s,b,d]   (A NT, B via ldmatrix.trans)
    mma_gemm<true, false><<<dim3(8, 8, 32), 256, SM_TOTAL>>>(
        (const bf16*)wHi, (const bf16*)wLo, (const bf16*)srcHi, (const bf16*)srcLo,
        out, nullptr, nullptr,
        1024, 32768, 32768, (long)1024 * 1024, 1024, 1024);
}

// round 9
// speedup vs baseline: 1.1487x; 1.0156x over previous
#include <cuda_runtime.h>
#include <cuda_bf16.h>
#include <cstdint>

typedef __nv_bfloat16 bf16;

#define S_ 1024
#define T_ 1024
#define B_ 32
#define D_ 1024
#define A_ 1024

// ---------------------------------------------------------------------------
// Scratch (device globals; allocation is forbidden)
// ---------------------------------------------------------------------------
__device__ __align__(16) bf16 g_srcHi[(size_t)S_ * B_ * D_];   // (S,B,D)
__device__ __align__(16) bf16 g_srcLo[(size_t)S_ * B_ * D_];
__device__ __align__(16) bf16 g_tgtHi[(size_t)T_ * B_ * D_];   // (T,B,D)
__device__ __align__(16) bf16 g_tgtLo[(size_t)T_ * B_ * D_];
__device__ __align__(16) bf16 g_mtHi[(size_t)A_ * D_];         // Mt[e,d] = sum_a W2[a,e]W1[a,d]
__device__ __align__(16) bf16 g_mtLo[(size_t)A_ * D_];
__device__ __align__(16) bf16 g_uHi[(size_t)S_ * B_ * A_];     // (S,B,A) u = src @ Mt^T
__device__ __align__(16) bf16 g_uLo[(size_t)S_ * B_ * A_];
__device__ __align__(16) float g_sc[(size_t)B_ * T_ * S_];     // (B,T,S) scores
__device__ __align__(16) bf16 g_wHi[(size_t)B_ * T_ * S_];     // softmax weights split
__device__ __align__(16) bf16 g_wLo[(size_t)B_ * T_ * S_];

// ---------------------------------------------------------------------------
// Portable tensor-core primitives (sm_80-level PTX: safe for compute_103 pass)
// ---------------------------------------------------------------------------
__device__ __forceinline__ uint32_t smem_u32(const void* p) {
    uint32_t a;
    asm("{ .reg .u64 t; cvta.to.shared.u64 t, %1; cvt.u32.u64 %0, t; }" : "=r"(a) : "l"(p));
    return a;
}

__device__ __forceinline__ void cpa16(uint32_t s, const void* g) {
    asm volatile("cp.async.cg.shared.global [%0], [%1], 16;" :: "r"(s), "l"(g));
}
#define CP_COMMIT() asm volatile("cp.async.commit_group;" ::: "memory")
#define CP_WAIT1()  asm volatile("cp.async.wait_group 1;" ::: "memory")

__device__ __forceinline__ void ldsm4(uint32_t* r, uint32_t a) {
    asm volatile("ldmatrix.sync.aligned.m8n8.x4.shared.b16 {%0,%1,%2,%3}, [%4];"
                 : "=r"(r[0]), "=r"(r[1]), "=r"(r[2]), "=r"(r[3]) : "r"(a));
}
__device__ __forceinline__ void ldsm4t(uint32_t* r, uint32_t a) {
    asm volatile("ldmatrix.sync.aligned.m8n8.x4.trans.shared.b16 {%0,%1,%2,%3}, [%4];"
                 : "=r"(r[0]), "=r"(r[1]), "=r"(r[2]), "=r"(r[3]) : "r"(a));
}
__device__ __forceinline__ void mma_bf16(float* c, const uint32_t* a, const uint32_t* b) {
    asm volatile("mma.sync.aligned.m16n8k16.row.col.f32.bf16.bf16.f32 "
                 "{%0,%1,%2,%3}, {%4,%5,%6,%7}, {%8,%9}, {%0,%1,%2,%3};"
                 : "+f"(c[0]), "+f"(c[1]), "+f"(c[2]), "+f"(c[3])
                 : "r"(a[0]), "r"(a[1]), "r"(a[2]), "r"(a[3]), "r"(b[0]), "r"(b[1]));
}

// ---------------------------------------------------------------------------
// Tiled bf16x3-split GEMM:  C[m,n](z) = sum_k A[m,k]*B[n,k]  (NT)
//   or, if BTRANS:          C[m,n](z) = sum_k A[m,k]*B[k,n]  (B via ldmatrix.trans)
// CTA tile 128x128x32, 8 warps (2x4 grid of 64x32 warp tiles), 3-stage ring,
// 2 CTAs/SM (barrier stagger). XOR-swizzled smem (no padding).
// Chunk body: sync -> first ldsm batch -> cp.async prefetch -> MMAs
// (prefetch issue burst hides under in-flight ldsm latency).
// acc += Ahi*Bhi + Ahi*Blo + Alo*Bhi.
// ---------------------------------------------------------------------------
#define HALF_B   8192           // one NT half (128x64B) or TR half (32x256B)
#define STAGE_B  32768          // Ahi, Alo, Bhi, Blo
#define SM_TOTAL (3 * STAGE_B)  // 98304 B per CTA

// NT tile store: 512 chunks of 16B (128 rows x 4 chunks), 256 threads -> 2 iters
__device__ __forceinline__ void load_nt(uint32_t sbase, const bf16* g, long ld, int tid) {
    #pragma unroll
    for (int i = 0; i < 2; i++) {
        const int c = tid + i * 256;
        const int row = c >> 2, ch = c & 3;
        const int sw = ch ^ ((row >> 1) & 3);
        cpa16(sbase + row * 64 + sw * 16, g + (long)row * ld + ch * 8);
    }
}
// TR tile store: 512 chunks (32 rows x 16 chunks)
__device__ __forceinline__ void load_tr(uint32_t sbase, const bf16* g, long ld, int tid) {
    #pragma unroll
    for (int i = 0; i < 2; i++) {
        const int c = tid + i * 256;
        const int row = c >> 4, ch = c & 15;
        const int sw = ch ^ (row & 7);
        cpa16(sbase + row * 256 + sw * 16, g + (long)row * ld + ch * 8);
    }
}

template <bool BTRANS, bool SPLITOUT>
__global__ __launch_bounds__(256, 2) void mma_gemm(
    const bf16* __restrict__ Ah, const bf16* __restrict__ Al,
    const bf16* __restrict__ Bh, const bf16* __restrict__ Bl,
    float* __restrict__ C, bf16* __restrict__ Oh, bf16* __restrict__ Ol,
    long lda, long ldb, long ldc, long aB, long bB, long cB)
{
    extern __shared__ char smem[];
    const uint32_t sb = smem_u32(smem);
    const int tid = threadIdx.x;
    const int lane = tid & 31, wid = tid >> 5;
    const int wy = wid >> 2, wx = wid & 3;        // 2 x 4 warps, 64x32 tiles
    const long m0 = (long)blockIdx.y * 128;
    const long n0 = (long)blockIdx.x * 128;
    const long z  = blockIdx.z;

    const bf16* pAh = Ah + z * aB + m0 * lda;
    const bf16* pAl = Al + z * aB + m0 * lda;
    const bf16* pBh = BTRANS ? (Bh + z * bB + n0) : (Bh + z * bB + n0 * ldb);
    const bf16* pBl = BTRANS ? (Bl + z * bB + n0) : (Bl + z * bB + n0 * ldb);

    float acc[4][4][4] = {};

    auto LOAD = [&](uint32_t st, int chunk) {
        const long k0 = (long)chunk * 32;
        load_nt(st,          pAh + k0, lda, tid);
        load_nt(st + HALF_B, pAl + k0, lda, tid);
        if (BTRANS) {
            load_tr(st + 2 * HALF_B, pBh + k0 * ldb, ldb, tid);
            load_tr(st + 3 * HALF_B, pBl + k0 * ldb, ldb, tid);
        } else {
            load_nt(st + 2 * HALF_B, pBh + k0, ldb, tid);
            load_nt(st + 3 * HALF_B, pBl + k0, ldb, tid);
        }
    };

    // Thread-constant ldsm address components (swizzle folded in)
    const int hi4 = lane >> 4;                     // 0/1 : 16B half selector
    const uint32_t aRowB = (uint32_t)(wy * 64 + (lane & 15)) * 64;
    const int sA = ((lane & 15) >> 1) & 3;
    const uint32_t bRowB = (uint32_t)(wx * 32 + (lane & 7) + (hi4 << 3)) * 64;
    const int sB = (((lane & 7) + (hi4 << 3)) >> 1) & 3;
    const int bSel = (lane >> 3) & 1;
    const uint32_t trRowB = (uint32_t)((lane & 7) + bSel * 8) * 256;
    const uint32_t trC0 = (uint32_t)((wx * 4 + 0 + hi4) ^ (lane & 7)) * 16;
    const uint32_t trC1 = (uint32_t)((wx * 4 + 2 + hi4) ^ (lane & 7)) * 16;

    LOAD(sb, 0); CP_COMMIT();
    LOAD(sb + STAGE_B, 1); CP_COMMIT();

    const uint32_t sEnd = sb + 3 * STAGE_B;
    uint32_t stCur = sb;                 // stage holding chunk c
    uint32_t stLd  = sb + 2 * STAGE_B;   // stage to receive chunk c+2

    const int NC = 32;   // K = 1024 / 32
    for (int c = 0; c < NC; c++) {
        CP_WAIT1();                       // chunk c resident (c+1 may fly)
        __syncthreads();                  // all warps done with freed stage

        // ---- peel: first fragment loads (k16 = 0) before the prefetch ----
        uint32_t bh[8], bl[8];
        if (!BTRANS) {
            const uint32_t cOff = (uint32_t)(bSel ^ sB) * 16;
            #pragma unroll
            for (int p = 0; p < 2; p++) {
                const uint32_t bd = stCur + 2 * HALF_B + bRowB + (uint32_t)p * 16 * 64 + cOff;
                ldsm4(&bh[p * 4], bd);
                ldsm4(&bl[p * 4], bd + HALF_B);
            }
        } else {
            ldsm4t(&bh[0], stCur + 2 * HALF_B + trRowB + trC0);
            ldsm4t(&bh[4], stCur + 2 * HALF_B + trRowB + trC1);
            ldsm4t(&bl[0], stCur + 3 * HALF_B + trRowB + trC0);
            ldsm4t(&bl[4], stCur + 3 * HALF_B + trRowB + trC1);
        }
        const uint32_t aOff0 = (uint32_t)(hi4 ^ sA) * 16;
        uint32_t ah0[4], al0[4];
        {
            const uint32_t ad = stCur + aRowB + aOff0;
            ldsm4(ah0, ad);
            ldsm4(al0, ad + HALF_B);
        }

        // ---- prefetch chunk c+2 (issue hides under in-flight ldsm) ----
        if (c + 2 < NC) LOAD(stLd, c + 2);
        CP_COMMIT();

        // ---- k16 = 0 compute ----
        #pragma unroll
        for (int nt = 0; nt < 4; nt++) {
            mma_bf16(acc[0][nt], ah0, &bh[nt * 2]);
            mma_bf16(acc[0][nt], ah0, &bl[nt * 2]);
            mma_bf16(acc[0][nt], al0, &bh[nt * 2]);
        }
        #pragma unroll
        for (int mt = 1; mt < 4; mt++) {
            uint32_t ah[4], al[4];
            const uint32_t ad = stCur + aRowB + (uint32_t)mt * 16 * 64 + aOff0;
            ldsm4(ah, ad);
            ldsm4(al, ad + HALF_B);
            #pragma unroll
            for (int nt = 0; nt < 4; nt++) {
                mma_bf16(acc[mt][nt], ah, &bh[nt * 2]);
                mma_bf16(acc[mt][nt], ah, &bl[nt * 2]);
                mma_bf16(acc[mt][nt], al, &bh[nt * 2]);
            }
        }

        // ---- k16 = 1 compute ----
        if (!BTRANS) {
            const uint32_t cOff = (uint32_t)((2 + bSel) ^ sB) * 16;
            #pragma unroll
            for (int p = 0; p < 2; p++) {
                const uint32_t bd = stCur + 2 * HALF_B + bRowB + (uint32_t)p * 16 * 64 + cOff;
                ldsm4(&bh[p * 4], bd);
                ldsm4(&bl[p * 4], bd + HALF_B);
            }
        } else {
            const uint32_t rOff = trRowB + 16 * 256;
            ldsm4t(&bh[0], stCur + 2 * HALF_B + rOff + trC0);
            ldsm4t(&bh[4], stCur + 2 * HALF_B + rOff + trC1);
            ldsm4t(&bl[0], stCur + 3 * HALF_B + rOff + trC0);
            ldsm4t(&bl[4], stCur + 3 * HALF_B + rOff + trC1);
        }
        const uint32_t aOff1 = (uint32_t)((2 + hi4) ^ sA) * 16;
        #pragma unroll
        for (int mt = 0; mt < 4; mt++) {
            uint32_t ah[4], al[4];
            const uint32_t ad = stCur + aRowB + (uint32_t)mt * 16 * 64 + aOff1;
            ldsm4(ah, ad);
            ldsm4(al, ad + HALF_B);
            #pragma unroll
            for (int nt = 0; nt < 4; nt++) {
                mma_bf16(acc[mt][nt], ah, &bh[nt * 2]);
                mma_bf16(acc[mt][nt], ah, &bl[nt * 2]);
                mma_bf16(acc[mt][nt], al, &bh[nt * 2]);
            }
        }

        // ---- rotate stages (no %3) ----
        stCur += STAGE_B; if (stCur == sEnd) stCur = sb;
        stLd  += STAGE_B; if (stLd  == sEnd) stLd  = sb;
    }

    // Epilogue (registers -> gmem)
    #pragma unroll
    for (int mt = 0; mt < 4; mt++) {
        #pragma unroll
        for (int half = 0; half < 2; half++) {
            const long row = m0 + wy * 64 + mt * 16 + (lane >> 2) + half * 8;
            #pragma unroll
            for (int nt = 0; nt < 4; nt++) {
                const long col = n0 + wx * 32 + nt * 8 + (lane & 3) * 2;
                const float v0 = acc[mt][nt][half * 2 + 0];
                const float v1 = acc[mt][nt][half * 2 + 1];
                if (SPLITOUT) {
                    bf16 h0 = __float2bfloat16_rn(v0), h1 = __float2bfloat16_rn(v1);
                    bf16 l0 = __float2bfloat16_rn(v0 - __bfloat162float(h0));
                    bf16 l1 = __float2bfloat16_rn(v1 - __bfloat162float(h1));
                    __nv_bfloat162 hv(h0, h1), lv(l0, l1);
                    *(uint32_t*)(Oh + z * cB + row * ldc + col) = *(uint32_t*)&hv;
                    *(uint32_t*)(Ol + z * cB + row * ldc + col) = *(uint32_t*)&lv;
                } else {
                    *(float2*)(C + z * cB + row * ldc + col) = make_float2(v0, v1);
                }
            }
        }
    }
}

// ---------------------------------------------------------------------------
// Elementwise fp32 -> bf16 hi/lo split
// ---------------------------------------------------------------------------
__global__ __launch_bounds__(256) void split_kernel(
    const float* __restrict__ x, bf16* __restrict__ hi, bf16* __restrict__ lo)
{
    const size_t i4 = (size_t)blockIdx.x * 256 + threadIdx.x;
    float4 v = ((const float4*)x)[i4];
    float f[4] = {v.x, v.y, v.z, v.w};
    uint32_t hw[2], lw[2];
    #pragma unroll
    for (int p = 0; p < 2; p++) {
        bf16 h0 = __float2bfloat16_rn(f[2 * p]), h1 = __float2bfloat16_rn(f[2 * p + 1]);
        bf16 l0 = __float2bfloat16_rn(f[2 * p] - __bfloat162float(h0));
        bf16 l1 = __float2bfloat16_rn(f[2 * p + 1] - __bfloat162float(h1));
        __nv_bfloat162 hv(h0, h1), lv(l0, l1);
        hw[p] = *(uint32_t*)&hv;
        lw[p] = *(uint32_t*)&lv;
    }
    ((uint2*)hi)[i4] = make_uint2(hw[0], hw[1]);
    ((uint2*)lo)[i4] = make_uint2(lw[0], lw[1]);
}

// ---------------------------------------------------------------------------
// TN SIMT fp32 GEMM: Mt[e,d] = sum_a W2[a,e]*W1[a,d], split-stored (2 GFLOP)
// ---------------------------------------------------------------------------
__global__ __launch_bounds__(256) void tn_split_kernel(
    const float* __restrict__ W2, const float* __restrict__ W1)
{
    __shared__ float As[16][128];
    __shared__ float Bs[16][128];

    const int tid = threadIdx.x;
    const int tx = tid & 15, ty = tid >> 4;
    const int m0 = blockIdx.y * 128, n0 = blockIdx.x * 128;
    const int r8 = tid >> 5, c4 = (tid & 31) * 4;

    float acc[8][8] = {};

    for (int k0 = 0; k0 < 1024; k0 += 16) {
        #pragma unroll
        for (int i = 0; i < 2; i++) {
            const int kr = k0 + r8 + i * 8;
            *(float4*)&As[r8 + i * 8][c4] = *(const float4*)(W2 + (size_t)kr * 1024 + m0 + c4);
            *(float4*)&Bs[r8 + i * 8][c4] = *(const float4*)(W1 + (size_t)kr * 1024 + n0 + c4);
        }
        __syncthreads();
        #pragma unroll
        for (int kk = 0; kk < 16; kk++) {
            float ra[8], rb[8];
            *(float4*)&ra[0] = *(const float4*)&As[kk][ty * 8];
            *(float4*)&ra[4] = *(const float4*)&As[kk][ty * 8 + 4];
            *(float4*)&rb[0] = *(const float4*)&Bs[kk][tx * 8];
            *(float4*)&rb[4] = *(const float4*)&Bs[kk][tx * 8 + 4];
            #pragma unroll
            for (int i = 0; i < 8; i++)
                #pragma unroll
                for (int j = 0; j < 8; j++)
                    acc[i][j] = fmaf(ra[i], rb[j], acc[i][j]);
        }
        __syncthreads();
    }

    #pragma unroll
    for (int i = 0; i < 8; i++) {
        const size_t base = (size_t)(m0 + ty * 8 + i) * 1024 + n0 + tx * 8;
        #pragma unroll
        for (int j = 0; j < 8; j++) {
            float f = acc[i][j];
            bf16 h = __float2bfloat16_rn(f);
            g_mtHi[base + j] = h;
            g_mtLo[base + j] = __float2bfloat16_rn(f - __bfloat162float(h));
        }
    }
}

// ---------------------------------------------------------------------------
// Softmax over contiguous rows of 1024; writes bf16 hi/lo split weights.
// ---------------------------------------------------------------------------
__global__ __launch_bounds__(256) void softmax_split_kernel(const float* __restrict__ sc)
{
    const size_t row = blockIdx.x;
    const float4* p = (const float4*)(sc + row * 1024);
    const int tid = threadIdx.x;
    __shared__ float sh[8];

    float4 v = p[tid];

    float m = fmaxf(fmaxf(v.x, v.y), fmaxf(v.z, v.w));
    #pragma unroll
    for (int o = 16; o; o >>= 1) m = fmaxf(m, __shfl_xor_sync(0xffffffffu, m, o));
    if ((tid & 31) == 0) sh[tid >> 5] = m;
    __syncthreads();
    m = sh[0];
    #pragma unroll
    for (int i = 1; i < 8; i++) m = fmaxf(m, sh[i]);
    __syncthreads();

    v.x = __expf(v.x - m); v.y = __expf(v.y - m);
    v.z = __expf(v.z - m); v.w = __expf(v.w - m);
    float s = v.x + v.y + v.z + v.w;
    #pragma unroll
    for (int o = 16; o; o >>= 1) s += __shfl_xor_sync(0xffffffffu, s, o);
    if ((tid & 31) == 0) sh[tid >> 5] = s;
    __syncthreads();
    s = sh[0] + sh[1] + sh[2] + sh[3] + sh[4] + sh[5] + sh[6] + sh[7];
    const float inv = 1.0f / s;

    float f[4] = {v.x * inv, v.y * inv, v.z * inv, v.w * inv};
    uint32_t hw[2], lw[2];
    #pragma unroll
    for (int q = 0; q < 2; q++) {
        bf16 h0 = __float2bfloat16_rn(f[2 * q]), h1 = __float2bfloat16_rn(f[2 * q + 1]);
        bf16 l0 = __float2bfloat16_rn(f[2 * q] - __bfloat162float(h0));
        bf16 l1 = __float2bfloat16_rn(f[2 * q + 1] - __bfloat162float(h1));
        __nv_bfloat162 hv(h0, h1), lv(l0, l1);
        hw[q] = *(uint32_t*)&hv;
        lw[q] = *(uint32_t*)&lv;
    }
    ((uint2*)(g_wHi + row * 1024))[tid] = make_uint2(hw[0], hw[1]);
    ((uint2*)(g_wLo + row * 1024))[tid] = make_uint2(lw[0], lw[1]);
}

// ---------------------------------------------------------------------------
// Host
// ---------------------------------------------------------------------------
extern "C" void kernel_launch(void* const* d_in, const int* in_sizes, int n_in,
                              void* d_out, int out_size)
{
    const float* src = (const float*)d_in[0];  // (S,B,D)
    const float* tgt = (const float*)d_in[1];  // (T,B,D)
    const float* W1  = (const float*)d_in[2];  // (A,D)
    const float* W2  = (const float*)d_in[3];  // (A,D)
    float* out = (float*)d_out;                // (T,B,D)

    void *srcHi, *srcLo, *tgtHi, *tgtLo, *mtHi, *mtLo, *uHi, *uLo, *sc, *wHi, *wLo;
    cudaGetSymbolAddress(&srcHi, g_srcHi); cudaGetSymbolAddress(&srcLo, g_srcLo);
    cudaGetSymbolAddress(&tgtHi, g_tgtHi); cudaGetSymbolAddress(&tgtLo, g_tgtLo);
    cudaGetSymbolAddress(&mtHi, g_mtHi);   cudaGetSymbolAddress(&mtLo, g_mtLo);
    cudaGetSymbolAddress(&uHi, g_uHi);     cudaGetSymbolAddress(&uLo, g_uLo);
    cudaGetSymbolAddress(&sc, g_sc);
    cudaGetSymbolAddress(&wHi, g_wHi);     cudaGetSymbolAddress(&wLo, g_wLo);

    cudaFuncSetAttribute(mma_gemm<false, true>,  cudaFuncAttributeMaxDynamicSharedMemorySize, SM_TOTAL);
    cudaFuncSetAttribute(mma_gemm<false, false>, cudaFuncAttributeMaxDynamicSharedMemorySize, SM_TOTAL);
    cudaFuncSetAttribute(mma_gemm<true,  false>, cudaFuncAttributeMaxDynamicSharedMemorySize, SM_TOTAL);

    // 1-2. split source & target into bf16 hi/lo
    split_kernel<<<(S_ * B_ * D_ / 4) / 256, 256>>>(src, (bf16*)srcHi, (bf16*)srcLo);
    split_kernel<<<(T_ * B_ * D_ / 4) / 256, 256>>>(tgt, (bf16*)tgtHi, (bf16*)tgtLo);
    // 3. Mt = W2^T W1 (fp32 SIMT), split-stored
    tn_split_kernel<<<dim3(8, 8), 256>>>(W2, W1);

    // 4. u[(s,b), e] = sum_d src[(s,b), d] * Mt[e, d]   (NT, M=32768, split output)
    mma_gemm<false, true><<<dim3(8, 256, 1), 256, SM_TOTAL>>>(
        (const bf16*)srcHi, (const bf16*)srcLo, (const bf16*)mtHi, (const bf16*)mtLo,
        nullptr, (bf16*)uHi, (bf16*)uLo,
        1024, 1024, 1024, 0, 0, 0);

    // 5. scores[b,t,s] = sum_e tgt[t,b,e] * u[s,b,e]   (NT, batched over b)
    mma_gemm<false, false><<<dim3(8, 8, 32), 256, SM_TOTAL>>>(
        (const bf16*)tgtHi, (const bf16*)tgtLo, (const bf16*)uHi, (const bf16*)uLo,
        (float*)sc, nullptr, nullptr,
        32768, 32768, 1024, 1024, 1024, (long)1024 * 1024);

    // 6. softmax over s (+ split weights)
    softmax_split_kernel<<<B_ * T_, 256>>>((const float*)sc);

    // 7. out[t,b,d] = sum_s w[b,t,s] * src[s,b,d]   (A NT, B via ldmatrix.trans)
    mma_gemm<true, false><<<dim3(8, 8, 32), 256, SM_TOTAL>>>(
        (const bf16*)wHi, (const bf16*)wLo, (const bf16*)srcHi, (const bf16*)srcLo,
        out, nullptr, nullptr,
        1024, 32768, 32768, (long)1024 * 1024, 1024, 1024);
}

// round 11
// speedup vs baseline: 1.2062x; 1.0501x over previous
#include <cuda_runtime.h>
#include <cuda_bf16.h>
#include <cstdint>

typedef __nv_bfloat16 bf16;

#define S_ 1024
#define T_ 1024
#define B_ 32
#define D_ 1024
#define A_ 1024

// ---------------------------------------------------------------------------
// Scratch (device globals; allocation is forbidden)
// ---------------------------------------------------------------------------
__device__ __align__(16) bf16 g_srcHi[(size_t)S_ * B_ * D_];   // (S,B,D)
__device__ __align__(16) bf16 g_srcLo[(size_t)S_ * B_ * D_];
__device__ __align__(16) bf16 g_tgtHi[(size_t)T_ * B_ * D_];   // (T,B,D)
__device__ __align__(16) bf16 g_tgtLo[(size_t)T_ * B_ * D_];
__device__ __align__(16) bf16 g_mtHi[(size_t)A_ * D_];         // Mt[e,d] = sum_a W2[a,e]W1[a,d]
__device__ __align__(16) bf16 g_mtLo[(size_t)A_ * D_];
__device__ __align__(16) float g_mtPart[4][(size_t)A_ * D_];   // split-K partials (16 MiB)
__device__ __align__(16) bf16 g_uHi[(size_t)S_ * B_ * A_];     // (S,B,A) u = src @ Mt^T
__device__ __align__(16) bf16 g_uLo[(size_t)S_ * B_ * A_];
__device__ __align__(16) float g_sc[(size_t)B_ * T_ * S_];     // (B,T,S) scores
__device__ __align__(16) bf16 g_wHi[(size_t)B_ * T_ * S_];     // softmax weights split
__device__ __align__(16) bf16 g_wLo[(size_t)B_ * T_ * S_];

// ---------------------------------------------------------------------------
// Portable tensor-core primitives (sm_80-level PTX: safe for compute_103 pass)
// ---------------------------------------------------------------------------
__device__ __forceinline__ uint32_t smem_u32(const void* p) {
    uint32_t a;
    asm("{ .reg .u64 t; cvta.to.shared.u64 t, %1; cvt.u32.u64 %0, t; }" : "=r"(a) : "l"(p));
    return a;
}

__device__ __forceinline__ void cpa16(uint32_t s, const void* g) {
    asm volatile("cp.async.cg.shared.global [%0], [%1], 16;" :: "r"(s), "l"(g));
}
#define CP_COMMIT() asm volatile("cp.async.commit_group;" ::: "memory")
#define CP_WAIT1()  asm volatile("cp.async.wait_group 1;" ::: "memory")

__device__ __forceinline__ void ldsm4(uint32_t* r, uint32_t a) {
    asm volatile("ldmatrix.sync.aligned.m8n8.x4.shared.b16 {%0,%1,%2,%3}, [%4];"
                 : "=r"(r[0]), "=r"(r[1]), "=r"(r[2]), "=r"(r[3]) : "r"(a));
}
__device__ __forceinline__ void ldsm4t(uint32_t* r, uint32_t a) {
    asm volatile("ldmatrix.sync.aligned.m8n8.x4.trans.shared.b16 {%0,%1,%2,%3}, [%4];"
                 : "=r"(r[0]), "=r"(r[1]), "=r"(r[2]), "=r"(r[3]) : "r"(a));
}
__device__ __forceinline__ void mma_bf16(float* c, const uint32_t* a, const uint32_t* b) {
    asm volatile("mma.sync.aligned.m16n8k16.row.col.f32.bf16.bf16.f32 "
                 "{%0,%1,%2,%3}, {%4,%5,%6,%7}, {%8,%9}, {%0,%1,%2,%3};"
                 : "+f"(c[0]), "+f"(c[1]), "+f"(c[2]), "+f"(c[3])
                 : "r"(a[0]), "r"(a[1]), "r"(a[2]), "r"(a[3]), "r"(b[0]), "r"(b[1]));
}

// ---------------------------------------------------------------------------
// Tiled bf16x3-split GEMM:  C[m,n](z) = sum_k A[m,k]*B[n,k]  (NT)
//   or, if BTRANS:          C[m,n](z) = sum_k A[m,k]*B[k,n]  (B via ldmatrix.trans)
// CTA tile 128x128x32, 8 warps (2x4 grid of 64x32 warp tiles), 3-stage ring,
// 2 CTAs/SM (barrier stagger). XOR-swizzled smem (no padding).
// Chunk body: wait -> sync -> peel ldsm -> cp.async prefetch -> MMAs.
// (Peel MUST be post-sync: cp.async data written by other threads is only
//  visible after the barrier where every thread has waited its own groups.)
// acc += Ahi*Bhi + Ahi*Blo + Alo*Bhi.
// ---------------------------------------------------------------------------
#define HALF_B   8192           // one NT half (128x64B) or TR half (32x256B)
#define STAGE_B  32768          // Ahi, Alo, Bhi, Blo
#define SM_TOTAL (3 * STAGE_B)  // 98304 B per CTA

// NT tile store: 512 chunks of 16B (128 rows x 4 chunks), 256 threads -> 2 iters
__device__ __forceinline__ void load_nt(uint32_t sbase, const bf16* g, long ld, int tid) {
    #pragma unroll
    for (int i = 0; i < 2; i++) {
        const int c = tid + i * 256;
        const int row = c >> 2, ch = c & 3;
        const int sw = ch ^ ((row >> 1) & 3);
        cpa16(sbase + row * 64 + sw * 16, g + (long)row * ld + ch * 8);
    }
}
// TR tile store: 512 chunks (32 rows x 16 chunks)
__device__ __forceinline__ void load_tr(uint32_t sbase, const bf16* g, long ld, int tid) {
    #pragma unroll
    for (int i = 0; i < 2; i++) {
        const int c = tid + i * 256;
        const int row = c >> 4, ch = c & 15;
        const int sw = ch ^ (row & 7);
        cpa16(sbase + row * 256 + sw * 16, g + (long)row * ld + ch * 8);
    }
}

template <bool BTRANS, bool SPLITOUT>
__global__ __launch_bounds__(256, 2) void mma_gemm(
    const bf16* __restrict__ Ah, const bf16* __restrict__ Al,
    const bf16* __restrict__ Bh, const bf16* __restrict__ Bl,
    float* __restrict__ C, bf16* __restrict__ Oh, bf16* __restrict__ Ol,
    long lda, long ldb, long ldc, long aB, long bB, long cB)
{
    extern __shared__ char smem[];
    const uint32_t sb = smem_u32(smem);
    const int tid = threadIdx.x;
    const int lane = tid & 31, wid = tid >> 5;
    const int wy = wid >> 2, wx = wid & 3;        // 2 x 4 warps, 64x32 tiles
    const long m0 = (long)blockIdx.y * 128;
    const long n0 = (long)blockIdx.x * 128;
    const long z  = blockIdx.z;

    const bf16* pAh = Ah + z * aB + m0 * lda;
    const bf16* pAl = Al + z * aB + m0 * lda;
    const bf16* pBh = BTRANS ? (Bh + z * bB + n0) : (Bh + z * bB + n0 * ldb);
    const bf16* pBl = BTRANS ? (Bl + z * bB + n0) : (Bl + z * bB + n0 * ldb);

    float acc[4][4][4] = {};

    auto LOAD = [&](uint32_t st, int chunk) {
        const long k0 = (long)chunk * 32;
        load_nt(st,          pAh + k0, lda, tid);
        load_nt(st + HALF_B, pAl + k0, lda, tid);
        if (BTRANS) {
            load_tr(st + 2 * HALF_B, pBh + k0 * ldb, ldb, tid);
            load_tr(st + 3 * HALF_B, pBl + k0 * ldb, ldb, tid);
        } else {
            load_nt(st + 2 * HALF_B, pBh + k0, ldb, tid);
            load_nt(st + 3 * HALF_B, pBl + k0, ldb, tid);
        }
    };

    // Thread-constant ldsm address components (swizzle folded in)
    const int hi4 = lane >> 4;                     // 0/1 : 16B half selector
    const uint32_t aRowB = (uint32_t)(wy * 64 + (lane & 15)) * 64;
    const int sA = ((lane & 15) >> 1) & 3;
    const uint32_t bRowB = (uint32_t)(wx * 32 + (lane & 7) + (hi4 << 3)) * 64;
    const int sB = (((lane & 7) + (hi4 << 3)) >> 1) & 3;
    const int bSel = (lane >> 3) & 1;
    const uint32_t trRowB = (uint32_t)((lane & 7) + bSel * 8) * 256;
    const uint32_t trC0 = (uint32_t)((wx * 4 + 0 + hi4) ^ (lane & 7)) * 16;
    const uint32_t trC1 = (uint32_t)((wx * 4 + 2 + hi4) ^ (lane & 7)) * 16;

    LOAD(sb, 0); CP_COMMIT();
    LOAD(sb + STAGE_B, 1); CP_COMMIT();

    const uint32_t sEnd = sb + 3 * STAGE_B;
    uint32_t stCur = sb;                 // stage holding chunk c
    uint32_t stLd  = sb + 2 * STAGE_B;   // stage to receive chunk c+2

    const int NC = 32;   // K = 1024 / 32
    for (int c = 0; c < NC; c++) {
        CP_WAIT1();                       // chunk c resident (c+1 may fly)
        __syncthreads();                  // visibility fence + stage-free point

        // ---- peel: first fragment loads (k16 = 0) before the prefetch ----
        uint32_t bh[8], bl[8];
        if (!BTRANS) {
            const uint32_t cOff = (uint32_t)(bSel ^ sB) * 16;
            #pragma unroll
            for (int p = 0; p < 2; p++) {
                const uint32_t bd = stCur + 2 * HALF_B + bRowB + (uint32_t)p * 16 * 64 + cOff;
                ldsm4(&bh[p * 4], bd);
                ldsm4(&bl[p * 4], bd + HALF_B);
            }
        } else {
            ldsm4t(&bh[0], stCur + 2 * HALF_B + trRowB + trC0);
            ldsm4t(&bh[4], stCur + 2 * HALF_B + trRowB + trC1);
            ldsm4t(&bl[0], stCur + 3 * HALF_B + trRowB + trC0);
            ldsm4t(&bl[4], stCur + 3 * HALF_B + trRowB + trC1);
        }
        const uint32_t aOff0 = (uint32_t)(hi4 ^ sA) * 16;
        uint32_t ah0[4], al0[4];
        {
            const uint32_t ad = stCur + aRowB + aOff0;
            ldsm4(ah0, ad);
            ldsm4(al0, ad + HALF_B);
        }

        // ---- prefetch chunk c+2 (issue hides under in-flight ldsm) ----
        if (c + 2 < NC) LOAD(stLd, c + 2);
        CP_COMMIT();

        // ---- k16 = 0 compute ----
        #pragma unroll
        for (int nt = 0; nt < 4; nt++) {
            mma_bf16(acc[0][nt], ah0, &bh[nt * 2]);
            mma_bf16(acc[0][nt], ah0, &bl[nt * 2]);
            mma_bf16(acc[0][nt], al0, &bh[nt * 2]);
        }
        #pragma unroll
        for (int mt = 1; mt < 4; mt++) {
            uint32_t ah[4], al[4];
            const uint32_t ad = stCur + aRowB + (uint32_t)mt * 16 * 64 + aOff0;
            ldsm4(ah, ad);
            ldsm4(al, ad + HALF_B);
            #pragma unroll
            for (int nt = 0; nt < 4; nt++) {
                mma_bf16(acc[mt][nt], ah, &bh[nt * 2]);
                mma_bf16(acc[mt][nt], ah, &bl[nt * 2]);
                mma_bf16(acc[mt][nt], al, &bh[nt * 2]);
            }
        }

        // ---- k16 = 1 compute ----
        if (!BTRANS) {
            const uint32_t cOff = (uint32_t)((2 + bSel) ^ sB) * 16;
            #pragma unroll
            for (int p = 0; p < 2; p++) {
                const uint32_t bd = stCur + 2 * HALF_B + bRowB + (uint32_t)p * 16 * 64 + cOff;
                ldsm4(&bh[p * 4], bd);
                ldsm4(&bl[p * 4], bd + HALF_B);
            }
        } else {
            const uint32_t rOff = trRowB + 16 * 256;
            ldsm4t(&bh[0], stCur + 2 * HALF_B + rOff + trC0);
            ldsm4t(&bh[4], stCur + 2 * HALF_B + rOff + trC1);
            ldsm4t(&bl[0], stCur + 3 * HALF_B + rOff + trC0);
            ldsm4t(&bl[4], stCur + 3 * HALF_B + rOff + trC1);
        }
        const uint32_t aOff1 = (uint32_t)((2 + hi4) ^ sA) * 16;
        #pragma unroll
        for (int mt = 0; mt < 4; mt++) {
            uint32_t ah[4], al[4];
            const uint32_t ad = stCur + aRowB + (uint32_t)mt * 16 * 64 + aOff1;
            ldsm4(ah, ad);
            ldsm4(al, ad + HALF_B);
            #pragma unroll
            for (int nt = 0; nt < 4; nt++) {
                mma_bf16(acc[mt][nt], ah, &bh[nt * 2]);
                mma_bf16(acc[mt][nt], ah, &bl[nt * 2]);
                mma_bf16(acc[mt][nt], al, &bh[nt * 2]);
            }
        }

        // ---- rotate stages (no %3) ----
        stCur += STAGE_B; if (stCur == sEnd) stCur = sb;
        stLd  += STAGE_B; if (stLd  == sEnd) stLd  = sb;
    }

    // Epilogue (registers -> gmem)
    #pragma unroll
    for (int mt = 0; mt < 4; mt++) {
        #pragma unroll
        for (int half = 0; half < 2; half++) {
            const long row = m0 + wy * 64 + mt * 16 + (lane >> 2) + half * 8;
            #pragma unroll
            for (int nt = 0; nt < 4; nt++) {
                const long col = n0 + wx * 32 + nt * 8 + (lane & 3) * 2;
                const float v0 = acc[mt][nt][half * 2 + 0];
                const float v1 = acc[mt][nt][half * 2 + 1];
                if (SPLITOUT) {
                    bf16 h0 = __float2bfloat16_rn(v0), h1 = __float2bfloat16_rn(v1);
                    bf16 l0 = __float2bfloat16_rn(v0 - __bfloat162float(h0));
                    bf16 l1 = __float2bfloat16_rn(v1 - __bfloat162float(h1));
                    __nv_bfloat162 hv(h0, h1), lv(l0, l1);
                    *(uint32_t*)(Oh + z * cB + row * ldc + col) = *(uint32_t*)&hv;
                    *(uint32_t*)(Ol + z * cB + row * ldc + col) = *(uint32_t*)&lv;
                } else {
                    *(float2*)(C + z * cB + row * ldc + col) = make_float2(v0, v1);
                }
            }
        }
    }
}

// ---------------------------------------------------------------------------
// Elementwise fp32 -> bf16 hi/lo split (2 float4 per thread for MLP)
// ---------------------------------------------------------------------------
__global__ __launch_bounds__(256) void split_kernel(
    const float* __restrict__ x, bf16* __restrict__ hi, bf16* __restrict__ lo)
{
    const size_t base = (size_t)blockIdx.x * 512 + threadIdx.x;
    float4 v0 = ((const float4*)x)[base];
    float4 v1 = ((const float4*)x)[base + 256];
    #pragma unroll
    for (int q = 0; q < 2; q++) {
        const float4 v = q ? v1 : v0;
        float f[4] = {v.x, v.y, v.z, v.w};
        uint32_t hw[2], lw[2];
        #pragma unroll
        for (int p = 0; p < 2; p++) {
            bf16 h0 = __float2bfloat16_rn(f[2 * p]), h1 = __float2bfloat16_rn(f[2 * p + 1]);
            bf16 l0 = __float2bfloat16_rn(f[2 * p] - __bfloat162float(h0));
            bf16 l1 = __float2bfloat16_rn(f[2 * p + 1] - __bfloat162float(h1));
            __nv_bfloat162 hv(h0, h1), lv(l0, l1);
            hw[p] = *(uint32_t*)&hv;
            lw[p] = *(uint32_t*)&lv;
        }
        ((uint2*)hi)[base + q * 256] = make_uint2(hw[0], hw[1]);
        ((uint2*)lo)[base + q * 256] = make_uint2(lw[0], lw[1]);
    }
}

// ---------------------------------------------------------------------------
// Split-K TN SIMT fp32 GEMM partials: part[z][e,d] = sum_{a in Kz} W2[a,e]W1[a,d]
// grid (8,8,4): 256 CTAs, K=256 per CTA.
// ---------------------------------------------------------------------------
__global__ __launch_bounds__(256) void tn_partial_kernel(
    const float* __restrict__ W2, const float* __restrict__ W1)
{
    __shared__ float As[16][128];
    __shared__ float Bs[16][128];

    const int tid = threadIdx.x;
    const int tx = tid & 15, ty = tid >> 4;
    const int m0 = blockIdx.y * 128, n0 = blockIdx.x * 128;
    const int kz = blockIdx.z * 256;
    const int r8 = tid >> 5, c4 = (tid & 31) * 4;

    float acc[8][8] = {};

    for (int k0 = kz; k0 < kz + 256; k0 += 16) {
        #pragma unroll
        for (int i = 0; i < 2; i++) {
            const int kr = k0 + r8 + i * 8;
            *(float4*)&As[r8 + i * 8][c4] = *(const float4*)(W2 + (size_t)kr * 1024 + m0 + c4);
            *(float4*)&Bs[r8 + i * 8][c4] = *(const float4*)(W1 + (size_t)kr * 1024 + n0 + c4);
        }
        __syncthreads();
        #pragma unroll
        for (int kk = 0; kk < 16; kk++) {
            float ra[8], rb[8];
            *(float4*)&ra[0] = *(const float4*)&As[kk][ty * 8];
            *(float4*)&ra[4] = *(const float4*)&As[kk][ty * 8 + 4];
            *(float4*)&rb[0] = *(const float4*)&Bs[kk][tx * 8];
            *(float4*)&rb[4] = *(const float4*)&Bs[kk][tx * 8 + 4];
            #pragma unroll
            for (int i = 0; i < 8; i++)
                #pragma unroll
                for (int j = 0; j < 8; j++)
                    acc[i][j] = fmaf(ra[i], rb[j], acc[i][j]);
        }
        __syncthreads();
    }

    float* part = g_mtPart[blockIdx.z];
    #pragma unroll
    for (int i = 0; i < 8; i++) {
        const size_t base = (size_t)(m0 + ty * 8 + i) * 1024 + n0 + tx * 8;
        *(float4*)(part + base)     = make_float4(acc[i][0], acc[i][1], acc[i][2], acc[i][3]);
        *(float4*)(part + base + 4) = make_float4(acc[i][4], acc[i][5], acc[i][6], acc[i][7]);
    }
}

// ---------------------------------------------------------------------------
// Reduce 4 Mt partials (fixed order -> deterministic) and split to bf16 hi/lo.
// 1M elements; float4 per thread.
// ---------------------------------------------------------------------------
__global__ __launch_bounds__(256) void mt_reduce_split_kernel()
{
    const size_t i4 = (size_t)blockIdx.x * 256 + threadIdx.x;
    float4 p0 = ((const float4*)g_mtPart[0])[i4];
    float4 p1 = ((const float4*)g_mtPart[1])[i4];
    float4 p2 = ((const float4*)g_mtPart[2])[i4];
    float4 p3 = ((const float4*)g_mtPart[3])[i4];
    float f[4] = {(p0.x + p1.x) + (p2.x + p3.x),
                  (p0.y + p1.y) + (p2.y + p3.y),
                  (p0.z + p1.z) + (p2.z + p3.z),
                  (p0.w + p1.w) + (p2.w + p3.w)};
    uint32_t hw[2], lw[2];
    #pragma unroll
    for (int p = 0; p < 2; p++) {
        bf16 h0 = __float2bfloat16_rn(f[2 * p]), h1 = __float2bfloat16_rn(f[2 * p + 1]);
        bf16 l0 = __float2bfloat16_rn(f[2 * p] - __bfloat162float(h0));
        bf16 l1 = __float2bfloat16_rn(f[2 * p + 1] - __bfloat162float(h1));
        __nv_bfloat162 hv(h0, h1), lv(l0, l1);
        hw[p] = *(uint32_t*)&hv;
        lw[p] = *(uint32_t*)&lv;
    }
    ((uint2*)g_mtHi)[i4] = make_uint2(hw[0], hw[1]);
    ((uint2*)g_mtLo)[i4] = make_uint2(lw[0], lw[1]);
}

// ---------------------------------------------------------------------------
// Softmax over contiguous rows of 1024; writes bf16 hi/lo split weights.
// ---------------------------------------------------------------------------
__global__ __launch_bounds__(256) void softmax_split_kernel(const float* __restrict__ sc)
{
    const size_t row = blockIdx.x;
    const float4* p = (const float4*)(sc + row * 1024);
    const int tid = threadIdx.x;
    __shared__ float sh[8];

    float4 v = p[tid];

    float m = fmaxf(fmaxf(v.x, v.y), fmaxf(v.z, v.w));
    #pragma unroll
    for (int o = 16; o; o >>= 1) m = fmaxf(m, __shfl_xor_sync(0xffffffffu, m, o));
    if ((tid & 31) == 0) sh[tid >> 5] = m;
    __syncthreads();
    m = sh[0];
    #pragma unroll
    for (int i = 1; i < 8; i++) m = fmaxf(m, sh[i]);
    __syncthreads();

    v.x = __expf(v.x - m); v.y = __expf(v.y - m);
    v.z = __expf(v.z - m); v.w = __expf(v.w - m);
    float s = v.x + v.y + v.z + v.w;
    #pragma unroll
    for (int o = 16; o; o >>= 1) s += __shfl_xor_sync(0xffffffffu, s, o);
    if ((tid & 31) == 0) sh[tid >> 5] = s;
    __syncthreads();
    s = sh[0] + sh[1] + sh[2] + sh[3] + sh[4] + sh[5] + sh[6] + sh[7];
    const float inv = 1.0f / s;

    float f[4] = {v.x * inv, v.y * inv, v.z * inv, v.w * inv};
    uint32_t hw[2], lw[2];
    #pragma unroll
    for (int q = 0; q < 2; q++) {
        bf16 h0 = __float2bfloat16_rn(f[2 * q]), h1 = __float2bfloat16_rn(f[2 * q + 1]);
        bf16 l0 = __float2bfloat16_rn(f[2 * q] - __bfloat162float(h0));
        bf16 l1 = __float2bfloat16_rn(f[2 * q + 1] - __bfloat162float(h1));
        __nv_bfloat162 hv(h0, h1), lv(l0, l1);
        hw[q] = *(uint32_t*)&hv;
        lw[q] = *(uint32_t*)&lv;
    }
    ((uint2*)(g_wHi + row * 1024))[tid] = make_uint2(hw[0], hw[1]);
    ((uint2*)(g_wLo + row * 1024))[tid] = make_uint2(lw[0], lw[1]);
}

// ---------------------------------------------------------------------------
// Host
// ---------------------------------------------------------------------------
extern "C" void kernel_launch(void* const* d_in, const int* in_sizes, int n_in,
                              void* d_out, int out_size)
{
    const float* src = (const float*)d_in[0];  // (S,B,D)
    const float* tgt = (const float*)d_in[1];  // (T,B,D)
    const float* W1  = (const float*)d_in[2];  // (A,D)
    const float* W2  = (const float*)d_in[3];  // (A,D)
    float* out = (float*)d_out;                // (T,B,D)

    void *srcHi, *srcLo, *tgtHi, *tgtLo, *mtHi, *mtLo, *uHi, *uLo, *sc, *wHi, *wLo;
    cudaGetSymbolAddress(&srcHi, g_srcHi); cudaGetSymbolAddress(&srcLo, g_srcLo);
    cudaGetSymbolAddress(&tgtHi, g_tgtHi); cudaGetSymbolAddress(&tgtLo, g_tgtLo);
    cudaGetSymbolAddress(&mtHi, g_mtHi);   cudaGetSymbolAddress(&mtLo, g_mtLo);
    cudaGetSymbolAddress(&uHi, g_uHi);     cudaGetSymbolAddress(&uLo, g_uLo);
    cudaGetSymbolAddress(&sc, g_sc);
    cudaGetSymbolAddress(&wHi, g_wHi);     cudaGetSymbolAddress(&wLo, g_wLo);

    cudaFuncSetAttribute(mma_gemm<false, true>,  cudaFuncAttributeMaxDynamicSharedMemorySize, SM_TOTAL);
    cudaFuncSetAttribute(mma_gemm<false, false>, cudaFuncAttributeMaxDynamicSharedMemorySize, SM_TOTAL);
    cudaFuncSetAttribute(mma_gemm<true,  false>, cudaFuncAttributeMaxDynamicSharedMemorySize, SM_TOTAL);

    // 1-2. split source & target into bf16 hi/lo (2 float4 per thread)
    split_kernel<<<(S_ * B_ * D_ / 4) / 512, 256>>>(src, (bf16*)srcHi, (bf16*)srcLo);
    split_kernel<<<(T_ * B_ * D_ / 4) / 512, 256>>>(tgt, (bf16*)tgtHi, (bf16*)tgtLo);
    // 3. Mt = W2^T W1 (fp32 SIMT, split-K x4) + deterministic reduce/split
    tn_partial_kernel<<<dim3(8, 8, 4), 256>>>(W2, W1);
    mt_reduce_split_kernel<<<(A_ * D_ / 4) / 256, 256>>>();

    // 4. u[(s,b), e] = sum_d src[(s,b), d] * Mt[e, d]   (NT, M=32768, split output)
    mma_gemm<false, true><<<dim3(8, 256, 1), 256, SM_TOTAL>>>(
        (const bf16*)srcHi, (const bf16*)srcLo, (const bf16*)mtHi, (const bf16*)mtLo,
        nullptr, (bf16*)uHi, (bf16*)uLo,
        1024, 1024, 1024, 0, 0, 0);

    // 5. scores[b,t,s] = sum_e tgt[t,b,e] * u[s,b,e]   (NT, batched over b)
    mma_gemm<false, false><<<dim3(8, 8, 32), 256, SM_TOTAL>>>(
        (const bf16*)tgtHi, (const bf16*)tgtLo, (const bf16*)uHi, (const bf16*)uLo,
        (float*)sc, nullptr, nullptr,
        32768, 32768, 1024, 1024, 1024, (long)1024 * 1024);

    // 6. softmax over s (+ split weights)
    softmax_split_kernel<<<B_ * T_, 256>>>((const float*)sc);

    // 7. out[t,b,d] = sum_s w[b,t,s] * src[s,b,d]   (A NT, B via ldmatrix.trans)
    mma_gemm<true, false><<<dim3(8, 8, 32), 256, SM_TOTAL>>>(
        (const bf16*)wHi, (const bf16*)wLo, (const bf16*)srcHi, (const bf16*)srcLo,
        out, nullptr, nullptr,
        1024, 32768, 32768, (long)1024 * 1024, 1024, 1024);
}

// round 12
// speedup vs baseline: 1.3288x; 1.1017x over previous
#include <cuda_runtime.h>
#include <cuda_bf16.h>
#include <cuda_fp16.h>
#include <cstdint>

typedef __nv_bfloat16 bf16;
typedef __half f16;

#define S_ 1024
#define T_ 1024
#define B_ 32
#define D_ 1024
#define A_ 1024

// ---------------------------------------------------------------------------
// Scratch (device globals; allocation is forbidden)
// ---------------------------------------------------------------------------
__device__ __align__(16) bf16 g_srcHi[(size_t)S_ * B_ * D_];   // (S,B,D) bf16 split (GEMM4)
__device__ __align__(16) bf16 g_srcLo[(size_t)S_ * B_ * D_];
__device__ __align__(16) f16  g_srcF16Hi[(size_t)S_ * B_ * D_];// fp16 split (GEMM7 B)
__device__ __align__(16) f16  g_srcF16Lo[(size_t)S_ * B_ * D_];
__device__ __align__(16) bf16 g_tgtHi[(size_t)T_ * B_ * D_];   // (T,B,D)
__device__ __align__(16) bf16 g_tgtLo[(size_t)T_ * B_ * D_];
__device__ __align__(16) bf16 g_mtHi[(size_t)A_ * D_];         // Mt[e,d]
__device__ __align__(16) bf16 g_mtLo[(size_t)A_ * D_];
__device__ __align__(16) float g_mtPart[4][(size_t)A_ * D_];   // split-K partials
__device__ __align__(16) bf16 g_uHi[(size_t)S_ * B_ * A_];     // (S,B,A)
__device__ __align__(16) bf16 g_uLo[(size_t)S_ * B_ * A_];
__device__ __align__(16) float g_sc[(size_t)B_ * T_ * S_];     // (B,T,S) scores
__device__ __align__(16) f16  g_wF16[(size_t)B_ * T_ * S_];    // softmax weights fp16

// ---------------------------------------------------------------------------
// Portable tensor-core primitives (sm_80-level PTX)
// ---------------------------------------------------------------------------
__device__ __forceinline__ uint32_t smem_u32(const void* p) {
    uint32_t a;
    asm("{ .reg .u64 t; cvta.to.shared.u64 t, %1; cvt.u32.u64 %0, t; }" : "=r"(a) : "l"(p));
    return a;
}

__device__ __forceinline__ void cpa16(uint32_t s, const void* g) {
    asm volatile("cp.async.cg.shared.global [%0], [%1], 16;" :: "r"(s), "l"(g));
}
#define CP_COMMIT() asm volatile("cp.async.commit_group;" ::: "memory")
#define CP_WAIT1()  asm volatile("cp.async.wait_group 1;" ::: "memory")

__device__ __forceinline__ void ldsm4(uint32_t* r, uint32_t a) {
    asm volatile("ldmatrix.sync.aligned.m8n8.x4.shared.b16 {%0,%1,%2,%3}, [%4];"
                 : "=r"(r[0]), "=r"(r[1]), "=r"(r[2]), "=r"(r[3]) : "r"(a));
}
__device__ __forceinline__ void ldsm4t(uint32_t* r, uint32_t a) {
    asm volatile("ldmatrix.sync.aligned.m8n8.x4.trans.shared.b16 {%0,%1,%2,%3}, [%4];"
                 : "=r"(r[0]), "=r"(r[1]), "=r"(r[2]), "=r"(r[3]) : "r"(a));
}
__device__ __forceinline__ void mma_bf16(float* c, const uint32_t* a, const uint32_t* b) {
    asm volatile("mma.sync.aligned.m16n8k16.row.col.f32.bf16.bf16.f32 "
                 "{%0,%1,%2,%3}, {%4,%5,%6,%7}, {%8,%9}, {%0,%1,%2,%3};"
                 : "+f"(c[0]), "+f"(c[1]), "+f"(c[2]), "+f"(c[3])
                 : "r"(a[0]), "r"(a[1]), "r"(a[2]), "r"(a[3]), "r"(b[0]), "r"(b[1]));
}
__device__ __forceinline__ void mma_f16(float* c, const uint32_t* a, const uint32_t* b) {
    asm volatile("mma.sync.aligned.m16n8k16.row.col.f32.f16.f16.f32 "
                 "{%0,%1,%2,%3}, {%4,%5,%6,%7}, {%8,%9}, {%0,%1,%2,%3};"
                 : "+f"(c[0]), "+f"(c[1]), "+f"(c[2]), "+f"(c[3])
                 : "r"(a[0]), "r"(a[1]), "r"(a[2]), "r"(a[3]), "r"(b[0]), "r"(b[1]));
}

// ---------------------------------------------------------------------------
// Shared tile loaders (XOR swizzle, no padding). 2B element types only.
// NT tile: 128 rows x 64B; TR tile: 32 rows x 256B.
// ---------------------------------------------------------------------------
__device__ __forceinline__ void load_nt(uint32_t sbase, const void* g, long ldBytes, int tid) {
    #pragma unroll
    for (int i = 0; i < 2; i++) {
        const int c = tid + i * 256;
        const int row = c >> 2, ch = c & 3;
        const int sw = ch ^ ((row >> 1) & 3);
        cpa16(sbase + row * 64 + sw * 16, (const char*)g + (long)row * ldBytes + ch * 16);
    }
}
__device__ __forceinline__ void load_tr(uint32_t sbase, const void* g, long ldBytes, int tid) {
    #pragma unroll
    for (int i = 0; i < 2; i++) {
        const int c = tid + i * 256;
        const int row = c >> 4, ch = c & 15;
        const int sw = ch ^ (row & 7);
        cpa16(sbase + row * 256 + sw * 16, (const char*)g + (long)row * ldBytes + ch * 16);
    }
}

// ---------------------------------------------------------------------------
// bf16x3-split GEMM (GEMM4/5): C[m,n](z) = sum_k A[m,k]*B[n,k]  (NT)
// CTA 128x128x32, 8 warps (2x4), 3-stage ring, 2 CTAs/SM.
// ---------------------------------------------------------------------------
#define HALF_B   8192
#define STAGE_B  32768
#define SM_TOTAL (3 * STAGE_B)

template <bool SPLITOUT>
__global__ __launch_bounds__(256, 2) void mma_gemm(
    const bf16* __restrict__ Ah, const bf16* __restrict__ Al,
    const bf16* __restrict__ Bh, const bf16* __restrict__ Bl,
    float* __restrict__ C, bf16* __restrict__ Oh, bf16* __restrict__ Ol,
    long lda, long ldb, long ldc, long aB, long bB, long cB)
{
    extern __shared__ char smem[];
    const uint32_t sb = smem_u32(smem);
    const int tid = threadIdx.x;
    const int lane = tid & 31, wid = tid >> 5;
    const int wy = wid >> 2, wx = wid & 3;
    const long m0 = (long)blockIdx.y * 128;
    const long n0 = (long)blockIdx.x * 128;
    const long z  = blockIdx.z;

    const bf16* pAh = Ah + z * aB + m0 * lda;
    const bf16* pAl = Al + z * aB + m0 * lda;
    const bf16* pBh = Bh + z * bB + n0 * ldb;
    const bf16* pBl = Bl + z * bB + n0 * ldb;

    float acc[4][4][4] = {};

    auto LOAD = [&](uint32_t st, int chunk) {
        const long k0 = (long)chunk * 32;
        load_nt(st,              pAh + k0, lda * 2, tid);
        load_nt(st + HALF_B,     pAl + k0, lda * 2, tid);
        load_nt(st + 2 * HALF_B, pBh + k0, ldb * 2, tid);
        load_nt(st + 3 * HALF_B, pBl + k0, ldb * 2, tid);
    };

    const int hi4 = lane >> 4;
    const uint32_t aRowB = (uint32_t)(wy * 64 + (lane & 15)) * 64;
    const int sA = ((lane & 15) >> 1) & 3;
    const uint32_t bRowB = (uint32_t)(wx * 32 + (lane & 7) + (hi4 << 3)) * 64;
    const int sB = (((lane & 7) + (hi4 << 3)) >> 1) & 3;
    const int bSel = (lane >> 3) & 1;

    LOAD(sb, 0); CP_COMMIT();
    LOAD(sb + STAGE_B, 1); CP_COMMIT();

    const uint32_t sEnd = sb + 3 * STAGE_B;
    uint32_t stCur = sb;
    uint32_t stLd  = sb + 2 * STAGE_B;

    const int NC = 32;
    for (int c = 0; c < NC; c++) {
        CP_WAIT1();
        __syncthreads();                  // visibility fence + stage-free point

        // peel: first fragment loads (k16 = 0) before the prefetch
        uint32_t bh[8], bl[8];
        {
            const uint32_t cOff = (uint32_t)(bSel ^ sB) * 16;
            #pragma unroll
            for (int p = 0; p < 2; p++) {
                const uint32_t bd = stCur + 2 * HALF_B + bRowB + (uint32_t)p * 16 * 64 + cOff;
                ldsm4(&bh[p * 4], bd);
                ldsm4(&bl[p * 4], bd + HALF_B);
            }
        }
        const uint32_t aOff0 = (uint32_t)(hi4 ^ sA) * 16;
        uint32_t ah0[4], al0[4];
        {
            const uint32_t ad = stCur + aRowB + aOff0;
            ldsm4(ah0, ad);
            ldsm4(al0, ad + HALF_B);
        }

        if (c + 2 < NC) LOAD(stLd, c + 2);
        CP_COMMIT();

        // k16 = 0
        #pragma unroll
        for (int nt = 0; nt < 4; nt++) {
            mma_bf16(acc[0][nt], ah0, &bh[nt * 2]);
            mma_bf16(acc[0][nt], ah0, &bl[nt * 2]);
            mma_bf16(acc[0][nt], al0, &bh[nt * 2]);
        }
        #pragma unroll
        for (int mt = 1; mt < 4; mt++) {
            uint32_t ah[4], al[4];
            const uint32_t ad = stCur + aRowB + (uint32_t)mt * 16 * 64 + aOff0;
            ldsm4(ah, ad);
            ldsm4(al, ad + HALF_B);
            #pragma unroll
            for (int nt = 0; nt < 4; nt++) {
                mma_bf16(acc[mt][nt], ah, &bh[nt * 2]);
                mma_bf16(acc[mt][nt], ah, &bl[nt * 2]);
                mma_bf16(acc[mt][nt], al, &bh[nt * 2]);
            }
        }

        // k16 = 1
        {
            const uint32_t cOff = (uint32_t)((2 + bSel) ^ sB) * 16;
            #pragma unroll
            for (int p = 0; p < 2; p++) {
                const uint32_t bd = stCur + 2 * HALF_B + bRowB + (uint32_t)p * 16 * 64 + cOff;
                ldsm4(&bh[p * 4], bd);
                ldsm4(&bl[p * 4], bd + HALF_B);
            }
        }
        const uint32_t aOff1 = (uint32_t)((2 + hi4) ^ sA) * 16;
        #pragma unroll
        for (int mt = 0; mt < 4; mt++) {
            uint32_t ah[4], al[4];
            const uint32_t ad = stCur + aRowB + (uint32_t)mt * 16 * 64 + aOff1;
            ldsm4(ah, ad);
            ldsm4(al, ad + HALF_B);
            #pragma unroll
            for (int nt = 0; nt < 4; nt++) {
                mma_bf16(acc[mt][nt], ah, &bh[nt * 2]);
                mma_bf16(acc[mt][nt], ah, &bl[nt * 2]);
                mma_bf16(acc[mt][nt], al, &bh[nt * 2]);
            }
        }

        stCur += STAGE_B; if (stCur == sEnd) stCur = sb;
        stLd  += STAGE_B; if (stLd  == sEnd) stLd  = sb;
    }

    #pragma unroll
    for (int mt = 0; mt < 4; mt++) {
        #pragma unroll
        for (int half = 0; half < 2; half++) {
            const long row = m0 + wy * 64 + mt * 16 + (lane >> 2) + half * 8;
            #pragma unroll
            for (int nt = 0; nt < 4; nt++) {
                const long col = n0 + wx * 32 + nt * 8 + (lane & 3) * 2;
                const float v0 = acc[mt][nt][half * 2 + 0];
                const float v1 = acc[mt][nt][half * 2 + 1];
                if (SPLITOUT) {
                    bf16 h0 = __float2bfloat16_rn(v0), h1 = __float2bfloat16_rn(v1);
                    bf16 l0 = __float2bfloat16_rn(v0 - __bfloat162float(h0));
                    bf16 l1 = __float2bfloat16_rn(v1 - __bfloat162float(h1));
                    __nv_bfloat162 hv(h0, h1), lv(l0, l1);
                    *(uint32_t*)(Oh + z * cB + row * ldc + col) = *(uint32_t*)&hv;
                    *(uint32_t*)(Ol + z * cB + row * ldc + col) = *(uint32_t*)&lv;
                } else {
                    *(float2*)(C + z * cB + row * ldc + col) = make_float2(v0, v1);
                }
            }
        }
    }
}

// ---------------------------------------------------------------------------
// fp16 GEMM7: out[t,d](b) = sum_s w[t,s] * src[s,d]   (A=w fp16 single NT,
// B=srcF16 hi/lo via ldsm.trans). 2 MMAs per fragment: w*Shi + w*Slo.
// CTA 128x128x32, 8 warps (2x4), 3-stage 24KB ring, 2 CTAs/SM.
// ---------------------------------------------------------------------------
#define F16_AT    8192          // w tile 128x64B
#define F16_BT    8192          // one src TR half 32x256B
#define F16_STAGE 24576
#define F16_SM    (3 * F16_STAGE)

__global__ __launch_bounds__(256, 2) void mma_gemm_wf16(
    const f16* __restrict__ W, const f16* __restrict__ Bh, const f16* __restrict__ Bl,
    float* __restrict__ C,
    long lda, long ldb, long ldc, long aB, long bB, long cB)
{
    extern __shared__ char smem[];
    const uint32_t sb = smem_u32(smem);
    const int tid = threadIdx.x;
    const int lane = tid & 31, wid = tid >> 5;
    const int wy = wid >> 2, wx = wid & 3;
    const long m0 = (long)blockIdx.y * 128;
    const long n0 = (long)blockIdx.x * 128;
    const long z  = blockIdx.z;

    const f16* pA  = W  + z * aB + m0 * lda;
    const f16* pBh = Bh + z * bB + n0;
    const f16* pBl = Bl + z * bB + n0;

    float acc[4][4][4] = {};

    auto LOAD = [&](uint32_t st, int chunk) {
        const long k0 = (long)chunk * 32;
        load_nt(st,                    pA + k0,        lda * 2, tid);
        load_tr(st + F16_AT,           pBh + k0 * ldb, ldb * 2, tid);
        load_tr(st + F16_AT + F16_BT,  pBl + k0 * ldb, ldb * 2, tid);
    };

    const int hi4 = lane >> 4;
    const uint32_t aRowB = (uint32_t)(wy * 64 + (lane & 15)) * 64;
    const int sA = ((lane & 15) >> 1) & 3;
    const int bSel = (lane >> 3) & 1;
    const uint32_t trRowB = (uint32_t)((lane & 7) + bSel * 8) * 256;
    const uint32_t trC0 = (uint32_t)((wx * 4 + 0 + hi4) ^ (lane & 7)) * 16;
    const uint32_t trC1 = (uint32_t)((wx * 4 + 2 + hi4) ^ (lane & 7)) * 16;

    LOAD(sb, 0); CP_COMMIT();
    LOAD(sb + F16_STAGE, 1); CP_COMMIT();

    const uint32_t sEnd = sb + 3 * F16_STAGE;
    uint32_t stCur = sb;
    uint32_t stLd  = sb + 2 * F16_STAGE;

    const int NC = 32;
    for (int c = 0; c < NC; c++) {
        CP_WAIT1();
        __syncthreads();

        // peel k16=0 fragments
        uint32_t bh[8], bl[8];
        ldsm4t(&bh[0], stCur + F16_AT + trRowB + trC0);
        ldsm4t(&bh[4], stCur + F16_AT + trRowB + trC1);
        ldsm4t(&bl[0], stCur + F16_AT + F16_BT + trRowB + trC0);
        ldsm4t(&bl[4], stCur + F16_AT + F16_BT + trRowB + trC1);
        const uint32_t aOff0 = (uint32_t)(hi4 ^ sA) * 16;
        uint32_t a0[4];
        ldsm4(a0, stCur + aRowB + aOff0);

        if (c + 2 < NC) LOAD(stLd, c + 2);
        CP_COMMIT();

        // k16 = 0
        #pragma unroll
        for (int nt = 0; nt < 4; nt++) {
            mma_f16(acc[0][nt], a0, &bh[nt * 2]);
            mma_f16(acc[0][nt], a0, &bl[nt * 2]);
        }
        #pragma unroll
        for (int mt = 1; mt < 4; mt++) {
            uint32_t a[4];
            ldsm4(a, stCur + aRowB + (uint32_t)mt * 16 * 64 + aOff0);
            #pragma unroll
            for (int nt = 0; nt < 4; nt++) {
                mma_f16(acc[mt][nt], a, &bh[nt * 2]);
                mma_f16(acc[mt][nt], a, &bl[nt * 2]);
            }
        }

        // k16 = 1
        {
            const uint32_t rOff = trRowB + 16 * 256;
            ldsm4t(&bh[0], stCur + F16_AT + rOff + trC0);
            ldsm4t(&bh[4], stCur + F16_AT + rOff + trC1);
            ldsm4t(&bl[0], stCur + F16_AT + F16_BT + rOff + trC0);
            ldsm4t(&bl[4], stCur + F16_AT + F16_BT + rOff + trC1);
        }
        const uint32_t aOff1 = (uint32_t)((2 + hi4) ^ sA) * 16;
        #pragma unroll
        for (int mt = 0; mt < 4; mt++) {
            uint32_t a[4];
            ldsm4(a, stCur + aRowB + (uint32_t)mt * 16 * 64 + aOff1);
            #pragma unroll
            for (int nt = 0; nt < 4; nt++) {
                mma_f16(acc[mt][nt], a, &bh[nt * 2]);
                mma_f16(acc[mt][nt], a, &bl[nt * 2]);
            }
        }

        stCur += F16_STAGE; if (stCur == sEnd) stCur = sb;
        stLd  += F16_STAGE; if (stLd  == sEnd) stLd  = sb;
    }

    #pragma unroll
    for (int mt = 0; mt < 4; mt++) {
        #pragma unroll
        for (int half = 0; half < 2; half++) {
            const long row = m0 + wy * 64 + mt * 16 + (lane >> 2) + half * 8;
            #pragma unroll
            for (int nt = 0; nt < 4; nt++) {
                const long col = n0 + wx * 32 + nt * 8 + (lane & 3) * 2;
                *(float2*)(C + z * cB + row * ldc + col) =
                    make_float2(acc[mt][nt][half * 2], acc[mt][nt][half * 2 + 1]);
            }
        }
    }
}

// ---------------------------------------------------------------------------
// src split: fp32 -> bf16 hi/lo + fp16 hi/lo (2 float4 per thread)
// ---------------------------------------------------------------------------
__global__ __launch_bounds__(256) void split_src_kernel(const float* __restrict__ x)
{
    const size_t base = (size_t)blockIdx.x * 512 + threadIdx.x;
    #pragma unroll
    for (int q = 0; q < 2; q++) {
        const size_t i4 = base + q * 256;
        float4 v = ((const float4*)x)[i4];
        float f[4] = {v.x, v.y, v.z, v.w};
        uint32_t bhw[2], blw[2], fhw[2], flw[2];
        #pragma unroll
        for (int p = 0; p < 2; p++) {
            bf16 h0 = __float2bfloat16_rn(f[2 * p]), h1 = __float2bfloat16_rn(f[2 * p + 1]);
            bf16 l0 = __float2bfloat16_rn(f[2 * p] - __bfloat162float(h0));
            bf16 l1 = __float2bfloat16_rn(f[2 * p + 1] - __bfloat162float(h1));
            __nv_bfloat162 hv(h0, h1), lv(l0, l1);
            bhw[p] = *(uint32_t*)&hv;
            blw[p] = *(uint32_t*)&lv;
            f16 g0 = __float2half_rn(f[2 * p]), g1 = __float2half_rn(f[2 * p + 1]);
            f16 m0 = __float2half_rn(f[2 * p] - __half2float(g0));
            f16 m1 = __float2half_rn(f[2 * p + 1] - __half2float(g1));
            __half2 gv(g0, g1), mv(m0, m1);
            fhw[p] = *(uint32_t*)&gv;
            flw[p] = *(uint32_t*)&mv;
        }
        ((uint2*)g_srcHi)[i4]    = make_uint2(bhw[0], bhw[1]);
        ((uint2*)g_srcLo)[i4]    = make_uint2(blw[0], blw[1]);
        ((uint2*)g_srcF16Hi)[i4] = make_uint2(fhw[0], fhw[1]);
        ((uint2*)g_srcF16Lo)[i4] = make_uint2(flw[0], flw[1]);
    }
}

// ---------------------------------------------------------------------------
// tgt split: fp32 -> bf16 hi/lo
// ---------------------------------------------------------------------------
__global__ __launch_bounds__(256) void split_tgt_kernel(const float* __restrict__ x)
{
    const size_t base = (size_t)blockIdx.x * 512 + threadIdx.x;
    #pragma unroll
    for (int q = 0; q < 2; q++) {
        const size_t i4 = base + q * 256;
        float4 v = ((const float4*)x)[i4];
        float f[4] = {v.x, v.y, v.z, v.w};
        uint32_t hw[2], lw[2];
        #pragma unroll
        for (int p = 0; p < 2; p++) {
            bf16 h0 = __float2bfloat16_rn(f[2 * p]), h1 = __float2bfloat16_rn(f[2 * p + 1]);
            bf16 l0 = __float2bfloat16_rn(f[2 * p] - __bfloat162float(h0));
            bf16 l1 = __float2bfloat16_rn(f[2 * p + 1] - __bfloat162float(h1));
            __nv_bfloat162 hv(h0, h1), lv(l0, l1);
            hw[p] = *(uint32_t*)&hv;
            lw[p] = *(uint32_t*)&lv;
        }
        ((uint2*)g_tgtHi)[i4] = make_uint2(hw[0], hw[1]);
        ((uint2*)g_tgtLo)[i4] = make_uint2(lw[0], lw[1]);
    }
}

// ---------------------------------------------------------------------------
// Split-K TN SIMT fp32 GEMM partials (grid 8x8x4, K=256 each)
// ---------------------------------------------------------------------------
__global__ __launch_bounds__(256) void tn_partial_kernel(
    const float* __restrict__ W2, const float* __restrict__ W1)
{
    __shared__ float As[16][128];
    __shared__ float Bs[16][128];

    const int tid = threadIdx.x;
    const int tx = tid & 15, ty = tid >> 4;
    const int m0 = blockIdx.y * 128, n0 = blockIdx.x * 128;
    const int kz = blockIdx.z * 256;
    const int r8 = tid >> 5, c4 = (tid & 31) * 4;

    float acc[8][8] = {};

    for (int k0 = kz; k0 < kz + 256; k0 += 16) {
        #pragma unroll
        for (int i = 0; i < 2; i++) {
            const int kr = k0 + r8 + i * 8;
            *(float4*)&As[r8 + i * 8][c4] = *(const float4*)(W2 + (size_t)kr * 1024 + m0 + c4);
            *(float4*)&Bs[r8 + i * 8][c4] = *(const float4*)(W1 + (size_t)kr * 1024 + n0 + c4);
        }
        __syncthreads();
        #pragma unroll
        for (int kk = 0; kk < 16; kk++) {
            float ra[8], rb[8];
            *(float4*)&ra[0] = *(const float4*)&As[kk][ty * 8];
            *(float4*)&ra[4] = *(const float4*)&As[kk][ty * 8 + 4];
            *(float4*)&rb[0] = *(const float4*)&Bs[kk][tx * 8];
            *(float4*)&rb[4] = *(const float4*)&Bs[kk][tx * 8 + 4];
            #pragma unroll
            for (int i = 0; i < 8; i++)
                #pragma unroll
                for (int j = 0; j < 8; j++)
                    acc[i][j] = fmaf(ra[i], rb[j], acc[i][j]);
        }
        __syncthreads();
    }

    float* part = g_mtPart[blockIdx.z];
    #pragma unroll
    for (int i = 0; i < 8; i++) {
        const size_t base = (size_t)(m0 + ty * 8 + i) * 1024 + n0 + tx * 8;
        *(float4*)(part + base)     = make_float4(acc[i][0], acc[i][1], acc[i][2], acc[i][3]);
        *(float4*)(part + base + 4) = make_float4(acc[i][4], acc[i][5], acc[i][6], acc[i][7]);
    }
}

// ---------------------------------------------------------------------------
// Reduce 4 Mt partials (fixed order) and split to bf16 hi/lo.
// ---------------------------------------------------------------------------
__global__ __launch_bounds__(256) void mt_reduce_split_kernel()
{
    const size_t i4 = (size_t)blockIdx.x * 256 + threadIdx.x;
    float4 p0 = ((const float4*)g_mtPart[0])[i4];
    float4 p1 = ((const float4*)g_mtPart[1])[i4];
    float4 p2 = ((const float4*)g_mtPart[2])[i4];
    float4 p3 = ((const float4*)g_mtPart[3])[i4];
    float f[4] = {(p0.x + p1.x) + (p2.x + p3.x),
                  (p0.y + p1.y) + (p2.y + p3.y),
                  (p0.z + p1.z) + (p2.z + p3.z),
                  (p0.w + p1.w) + (p2.w + p3.w)};
    uint32_t hw[2], lw[2];
    #pragma unroll
    for (int p = 0; p < 2; p++) {
        bf16 h0 = __float2bfloat16_rn(f[2 * p]), h1 = __float2bfloat16_rn(f[2 * p + 1]);
        bf16 l0 = __float2bfloat16_rn(f[2 * p] - __bfloat162float(h0));
        bf16 l1 = __float2bfloat16_rn(f[2 * p + 1] - __bfloat162float(h1));
        __nv_bfloat162 hv(h0, h1), lv(l0, l1);
        hw[p] = *(uint32_t*)&hv;
        lw[p] = *(uint32_t*)&lv;
    }
    ((uint2*)g_mtHi)[i4] = make_uint2(hw[0], hw[1]);
    ((uint2*)g_mtLo)[i4] = make_uint2(lw[0], lw[1]);
}

// ---------------------------------------------------------------------------
// Softmax over contiguous rows of 1024; writes fp16 weights.
// ---------------------------------------------------------------------------
__global__ __launch_bounds__(256) void softmax_f16_kernel(const float* __restrict__ sc)
{
    const size_t row = blockIdx.x;
    const float4* p = (const float4*)(sc + row * 1024);
    const int tid = threadIdx.x;
    __shared__ float sh[8];

    float4 v = p[tid];

    float m = fmaxf(fmaxf(v.x, v.y), fmaxf(v.z, v.w));
    #pragma unroll
    for (int o = 16; o; o >>= 1) m = fmaxf(m, __shfl_xor_sync(0xffffffffu, m, o));
    if ((tid & 31) == 0) sh[tid >> 5] = m;
    __syncthreads();
    m = sh[0];
    #pragma unroll
    for (int i = 1; i < 8; i++) m = fmaxf(m, sh[i]);
    __syncthreads();

    v.x = __expf(v.x - m); v.y = __expf(v.y - m);
    v.z = __expf(v.z - m); v.w = __expf(v.w - m);
    float s = v.x + v.y + v.z + v.w;
    #pragma unroll
    for (int o = 16; o; o >>= 1) s += __shfl_xor_sync(0xffffffffu, s, o);
    if ((tid & 31) == 0) sh[tid >> 5] = s;
    __syncthreads();
    s = sh[0] + sh[1] + sh[2] + sh[3] + sh[4] + sh[5] + sh[6] + sh[7];
    const float inv = 1.0f / s;

    __half2 w01(__float2half_rn(v.x * inv), __float2half_rn(v.y * inv));
    __half2 w23(__float2half_rn(v.z * inv), __float2half_rn(v.w * inv));
    ((uint2*)(g_wF16 + row * 1024))[tid] = make_uint2(*(uint32_t*)&w01, *(uint32_t*)&w23);
}

// ---------------------------------------------------------------------------
// Host
// ---------------------------------------------------------------------------
extern "C" void kernel_launch(void* const* d_in, const int* in_sizes, int n_in,
                              void* d_out, int out_size)
{
    const float* src = (const float*)d_in[0];  // (S,B,D)
    const float* tgt = (const float*)d_in[1];  // (T,B,D)
    const float* W1  = (const float*)d_in[2];  // (A,D)
    const float* W2  = (const float*)d_in[3];  // (A,D)
    float* out = (float*)d_out;                // (T,B,D)

    void *srcHi, *srcLo, *sF16Hi, *sF16Lo, *tgtHi, *tgtLo, *mtHi, *mtLo, *uHi, *uLo, *sc, *wF16;
    cudaGetSymbolAddress(&srcHi, g_srcHi);   cudaGetSymbolAddress(&srcLo, g_srcLo);
    cudaGetSymbolAddress(&sF16Hi, g_srcF16Hi); cudaGetSymbolAddress(&sF16Lo, g_srcF16Lo);
    cudaGetSymbolAddress(&tgtHi, g_tgtHi);   cudaGetSymbolAddress(&tgtLo, g_tgtLo);
    cudaGetSymbolAddress(&mtHi, g_mtHi);     cudaGetSymbolAddress(&mtLo, g_mtLo);
    cudaGetSymbolAddress(&uHi, g_uHi);       cudaGetSymbolAddress(&uLo, g_uLo);
    cudaGetSymbolAddress(&sc, g_sc);         cudaGetSymbolAddress(&wF16, g_wF16);

    cudaFuncSetAttribute(mma_gemm<true>,  cudaFuncAttributeMaxDynamicSharedMemorySize, SM_TOTAL);
    cudaFuncSetAttribute(mma_gemm<false>, cudaFuncAttributeMaxDynamicSharedMemorySize, SM_TOTAL);
    cudaFuncSetAttribute(mma_gemm_wf16,   cudaFuncAttributeMaxDynamicSharedMemorySize, F16_SM);

    // 1-2. splits
    split_src_kernel<<<(S_ * B_ * D_ / 4) / 512, 256>>>(src);
    split_tgt_kernel<<<(T_ * B_ * D_ / 4) / 512, 256>>>(tgt);
    // 3. Mt = W2^T W1 (split-K x4 + deterministic reduce/split)
    tn_partial_kernel<<<dim3(8, 8, 4), 256>>>(W2, W1);
    mt_reduce_split_kernel<<<(A_ * D_ / 4) / 256, 256>>>();

    // 4. u[(s,b), e] = sum_d src * Mt  (NT, M=32768, split output)
    mma_gemm<true><<<dim3(8, 256, 1), 256, SM_TOTAL>>>(
        (const bf16*)srcHi, (const bf16*)srcLo, (const bf16*)mtHi, (const bf16*)mtLo,
        nullptr, (bf16*)uHi, (bf16*)uLo,
        1024, 1024, 1024, 0, 0, 0);

    // 5. scores[b,t,s] = sum_e tgt * u  (NT batched over b)
    mma_gemm<false><<<dim3(8, 8, 32), 256, SM_TOTAL>>>(
        (const bf16*)tgtHi, (const bf16*)tgtLo, (const bf16*)uHi, (const bf16*)uLo,
        (float*)sc, nullptr, nullptr,
        32768, 32768, 1024, 1024, 1024, (long)1024 * 1024);

    // 6. softmax over s -> fp16 weights
    softmax_f16_kernel<<<B_ * T_, 256>>>((const float*)sc);

    // 7. out[t,b,d] = sum_s w[b,t,s] * src[s,b,d]   (fp16 path, 2 MMAs)
    mma_gemm_wf16<<<dim3(8, 8, 32), 256, F16_SM>>>(
        (const f16*)wF16, (const f16*)sF16Hi, (const f16*)sF16Lo, out,
        1024, 32768, 32768, (long)1024 * 1024, 1024, 1024);
}